// round 14
// baseline (speedup 1.0000x reference)
#include <cuda_runtime.h>
#include <cuda_bf16.h>
#include <math.h>
#include <stdint.h>

// ---------------- problem constants ----------------
#define BB 2
#define SS 2048
#define HID 5120
#define NH 32
#define DNOPE 128
#define DROPE 64
#define DV 128
#define DQ 192
#define QRANK 1536
#define KVRANK 512
#define MTOK (BB*SS)            // 4096
#define KVAOUT (KVRANK+DROPE)   // 576
#define KVAPAD 640              // kv_a rows padded to /128
#define W1R (QRANK+KVAPAD)      // 2176 combined q_a+kv_a output dim
#define QBOUT (NH*DQ)           // 6144
#define KVBOUT (NH*(DNOPE+DV))  // 8192
#define ODIM  (NH*DV)           // 4096

typedef __nv_bfloat16 bf16;

// ---------------- scratch (static device, allocation-free) ----------------
__device__ float g_c1  [(size_t)MTOK*W1R];     // [q_c | ckv] combined
__device__ float g_q   [(size_t)MTOK*QBOUT];
__device__ float g_kv  [(size_t)MTOK*KVBOUT];
// bf16 hi/lo operand buffers (projections)
__device__ bf16 g_hidh[(size_t)MTOK*HID],   g_hidl[(size_t)MTOK*HID];
__device__ bf16 g_w1h [(size_t)W1R*HID],    g_w1l [(size_t)W1R*HID];   // [qaw ; kvaw(pad)]
__device__ bf16 g_qbwh[(size_t)QBOUT*QRANK],g_qbwl[(size_t)QBOUT*QRANK];
__device__ bf16 g_kvbwh[(size_t)KVBOUT*KVRANK], g_kvbwl[(size_t)KVBOUT*KVRANK];
__device__ bf16 g_owh [(size_t)HID*ODIM],   g_owl [(size_t)HID*ODIM];
__device__ bf16 g_qch [(size_t)MTOK*QRANK], g_qcl [(size_t)MTOK*QRANK];
__device__ bf16 g_cnh [(size_t)MTOK*KVRANK],g_cnl [(size_t)MTOK*KVRANK];
__device__ bf16 g_ath [(size_t)MTOK*ODIM],  g_atl [(size_t)MTOK*ODIM];
// bf16 hi/lo attention operands [b,h][s][*]
__device__ bf16 g_Qhh[(size_t)BB*NH*SS*DQ], g_Qhl[(size_t)BB*NH*SS*DQ];
__device__ bf16 g_Khh[(size_t)BB*NH*SS*DQ], g_Khl[(size_t)BB*NH*SS*DQ];
__device__ bf16 g_Vhh[(size_t)BB*NH*SS*DV], g_Vhl[(size_t)BB*NH*SS*DV];

// ---------------- warp-MMA helpers (plain sm_103-legal PTX) ----------------
__device__ __forceinline__ uint32_t s2u(const void* p) {
    uint32_t a;
    asm("{ .reg .u64 t; cvta.to.shared.u64 t, %1; cvt.u32.u64 %0, t; }" : "=r"(a) : "l"(p));
    return a;
}
#define SWZ128(off) ((off) ^ (((off) >> 3) & 0x70))   // 128B-row panels
#define SWZV(off)   ((off) ^ (((off) >> 4) & 0x70))   // 256B-row V panel

__device__ __forceinline__ void ldmx4(uint32_t r[4], uint32_t a) {
    asm volatile("ldmatrix.sync.aligned.m8n8.x4.shared.b16 {%0,%1,%2,%3}, [%4];"
        : "=r"(r[0]), "=r"(r[1]), "=r"(r[2]), "=r"(r[3]) : "r"(a));
}
__device__ __forceinline__ void ldmx2(uint32_t r[2], uint32_t a) {
    asm volatile("ldmatrix.sync.aligned.m8n8.x2.shared.b16 {%0,%1}, [%2];"
        : "=r"(r[0]), "=r"(r[1]) : "r"(a));
}
__device__ __forceinline__ void ldmx2t(uint32_t r[2], uint32_t a) {
    asm volatile("ldmatrix.sync.aligned.m8n8.x2.trans.shared.b16 {%0,%1}, [%2];"
        : "=r"(r[0]), "=r"(r[1]) : "r"(a));
}
__device__ __forceinline__ void mma16816(float c[4], const uint32_t a[4], const uint32_t b[2]) {
    asm volatile(
        "mma.sync.aligned.m16n8k16.row.col.f32.bf16.bf16.f32 "
        "{%0,%1,%2,%3}, {%4,%5,%6,%7}, {%8,%9}, {%0,%1,%2,%3};"
        : "+f"(c[0]), "+f"(c[1]), "+f"(c[2]), "+f"(c[3])
        : "r"(a[0]), "r"(a[1]), "r"(a[2]), "r"(a[3]), "r"(b[0]), "r"(b[1]));
}
__device__ __forceinline__ uint32_t packbf2(float lo, float hi) {
    __nv_bfloat162 t = __floats2bfloat162_rn(lo, hi);
    return *reinterpret_cast<uint32_t*>(&t);
}
__device__ __forceinline__ void cpa16(uint32_t dst, const void* src) {
    asm volatile("cp.async.cg.shared.global [%0], [%1], 16;" :: "r"(dst), "l"(src));
}
#define CPA_COMMIT() asm volatile("cp.async.commit_group;" ::: "memory")
#define CPA_WAIT1()  asm volatile("cp.async.wait_group 1;" ::: "memory")
#define CPA_WAIT0()  asm volatile("cp.async.wait_group 0;" ::: "memory")

// ===== split-bf16 HMMA GEMM, 128x128 tile, 2-stage cp.async, 1 barrier/chunk =====
// C[m,n] = sum_k A[m,k]*B[n,k]; A,B as (hi,lo) bf16 pairs. M,N %128; K %64.
#define TM 128
#define TN 128
#define TKC 64
#define SM_AH 0
#define SM_AL 16384
#define SM_BH 32768
#define SM_BL 49152
#define STG_B 65536
#define GEMM_SMEM (2 * STG_B)   // 131072

__global__ __launch_bounds__(256, 1)
void gemm_tc(const bf16* __restrict__ Ah, const bf16* __restrict__ Al,
             const bf16* __restrict__ Bh, const bf16* __restrict__ Bl,
             float* __restrict__ C, int K, int ldc)
{
    extern __shared__ char smem[];
    const uint32_t sb = s2u(smem);
    const int tid = threadIdx.x, wid = tid >> 5, lid = tid & 31;
    const int m0 = blockIdx.y * TM, n0 = blockIdx.x * TN;
    const int wm = wid & 1, wn = wid >> 1;

    const int grow = tid >> 1;
    const int half = tid & 1;
    const uint4* rAh = reinterpret_cast<const uint4*>(Ah + (size_t)(m0 + grow) * K);
    const uint4* rAl = reinterpret_cast<const uint4*>(Al + (size_t)(m0 + grow) * K);
    const uint4* rBh = reinterpret_cast<const uint4*>(Bh + (size_t)(n0 + grow) * K);
    const uint4* rBl = reinterpret_cast<const uint4*>(Bl + (size_t)(n0 + grow) * K);

    uint32_t soff[4];
    #pragma unroll
    for (int j = 0; j < 4; j++)
        soff[j] = SWZ128((uint32_t)(grow * 128 + half * 64 + j * 16));

    float c[4][4][4];
    #pragma unroll
    for (int mt = 0; mt < 4; mt++)
        #pragma unroll
        for (int nt = 0; nt < 4; nt++)
            #pragma unroll
            for (int e = 0; e < 4; e++) c[mt][nt][e] = 0.f;

    const int arow = wm * 64 + (lid & 15);
    const int aq   = lid >> 4;
    // B via ldmatrix.x4: two 16-row groups per warp (rows wn*32 + nt2*16 + ...)
    const int brow2 = wn * 32 + ((lid >> 4) << 3) + (lid & 7);
    const int bq2   = (lid >> 3) & 1;

    // prologue: chunk 0 -> stage 0
    {
        const int base = half * 4;
        #pragma unroll
        for (int j = 0; j < 4; j++) {
            cpa16(sb + SM_AH + soff[j], rAh + base + j);
            cpa16(sb + SM_AL + soff[j], rAl + base + j);
            cpa16(sb + SM_BH + soff[j], rBh + base + j);
            cpa16(sb + SM_BL + soff[j], rBl + base + j);
        }
        CPA_COMMIT();
    }

    const int nch = K / TKC;
    for (int ch = 0; ch < nch; ch++) {
        const uint32_t scur = sb + (uint32_t)(ch & 1) * STG_B;
        CPA_WAIT0();        // chunk ch complete (only pending group)
        __syncthreads();    // all threads done with prev stage reads + data visible
        if (ch + 1 < nch) { // prefetch ch+1 into other stage (safe: post-barrier)
            const uint32_t snxt = sb + (uint32_t)((ch + 1) & 1) * STG_B;
            const int base = (ch + 1) * (TKC / 8) + half * 4;
            #pragma unroll
            for (int j = 0; j < 4; j++) {
                cpa16(snxt + SM_AH + soff[j], rAh + base + j);
                cpa16(snxt + SM_AL + soff[j], rAl + base + j);
                cpa16(snxt + SM_BH + soff[j], rBh + base + j);
                cpa16(snxt + SM_BL + soff[j], rBl + base + j);
            }
            CPA_COMMIT();
        }

        #pragma unroll
        for (int ks = 0; ks < 4; ks++) {
            uint32_t ah[4][4], al[4][4];
            #pragma unroll
            for (int mt = 0; mt < 4; mt++) {
                const uint32_t off = SWZ128((uint32_t)((arow + mt * 16) * 128 + (ks * 2 + aq) * 16));
                ldmx4(ah[mt], scur + SM_AH + off);
                ldmx4(al[mt], scur + SM_AL + off);
            }
            #pragma unroll
            for (int nt2 = 0; nt2 < 2; nt2++) {
                uint32_t bh4[4], bl4[4];
                const uint32_t off = SWZ128((uint32_t)((brow2 + nt2 * 16) * 128 + (ks * 2 + bq2) * 16));
                ldmx4(bh4, scur + SM_BH + off);
                ldmx4(bl4, scur + SM_BL + off);
                #pragma unroll
                for (int mt = 0; mt < 4; mt++) {
                    mma16816(c[mt][nt2 * 2], ah[mt], bh4);
                    mma16816(c[mt][nt2 * 2], ah[mt], bl4);
                    mma16816(c[mt][nt2 * 2], al[mt], bh4);
                    mma16816(c[mt][nt2 * 2 + 1], ah[mt], bh4 + 2);
                    mma16816(c[mt][nt2 * 2 + 1], ah[mt], bl4 + 2);
                    mma16816(c[mt][nt2 * 2 + 1], al[mt], bh4 + 2);
                }
            }
        }
    }

    const int mbase = m0 + wm * 64 + (lid >> 2);
    const int nbase = n0 + wn * 32 + (lid & 3) * 2;
    #pragma unroll
    for (int mt = 0; mt < 4; mt++)
        #pragma unroll
        for (int nt = 0; nt < 4; nt++) {
            float* p0 = C + (size_t)(mbase + mt * 16) * ldc + nbase + nt * 8;
            float* p1 = p0 + 8 * ldc;
            *reinterpret_cast<float2*>(p0) = make_float2(c[mt][nt][0], c[mt][nt][1]);
            *reinterpret_cast<float2*>(p1) = make_float2(c[mt][nt][2], c[mt][nt][3]);
        }
}

// ---------------- fp32 -> (hi,lo) bf16 conversions ----------------
__global__ __launch_bounds__(256)
void cvt_pair_k(const float* __restrict__ x, bf16* __restrict__ h,
                bf16* __restrict__ l, size_t n)
{
    const size_t i = (size_t)blockIdx.x * 256 + threadIdx.x;
    if (i >= n) return;
    const float v = x[i];
    const bf16 hh = __float2bfloat16(v);
    h[i] = hh;
    l[i] = __float2bfloat16(v - __bfloat162float(hh));
}

__global__ __launch_bounds__(256)
void cvt_pad_k(const float* __restrict__ x, bf16* __restrict__ h,
               bf16* __restrict__ l, int rows, int cols, int padrows)
{
    const size_t i = (size_t)blockIdx.x * 256 + threadIdx.x;
    if (i >= (size_t)padrows * cols) return;
    const int r = (int)(i / cols);
    const float v = (r < rows) ? x[i] : 0.f;
    const bf16 hh = __float2bfloat16(v);
    h[i] = hh;
    l[i] = __float2bfloat16(v - __bfloat162float(hh));
}

// ---------------- RMSNorm -> (hi,lo) bf16 ----------------
__global__ __launch_bounds__(256)
void rmsnorm_pair_k(const float* __restrict__ x, const float* __restrict__ w,
                    bf16* __restrict__ yh, bf16* __restrict__ yl,
                    int n, int in_stride)
{
    const int row = blockIdx.x;
    const float* xr = x + (size_t)row * in_stride;
    bf16* yhr = yh + (size_t)row * n;
    bf16* ylr = yl + (size_t)row * n;
    __shared__ float red[256];
    float s = 0.f;
    for (int i = threadIdx.x; i < n; i += 256) { float v = xr[i]; s += v * v; }
    red[threadIdx.x] = s; __syncthreads();
    for (int o = 128; o; o >>= 1) {
        if (threadIdx.x < o) red[threadIdx.x] += red[threadIdx.x + o];
        __syncthreads();
    }
    const float r = rsqrtf(red[0] / n + 1e-6f);
    for (int i = threadIdx.x; i < n; i += 256) {
        const float v = xr[i] * r * w[i];
        const bf16 hh = __float2bfloat16(v);
        yhr[i] = hh;
        ylr[i] = __float2bfloat16(v - __bfloat162float(hh));
    }
}

// ------- build Q (RoPE + scale) -> bf16 hi/lo [b,h,s,192] -------
__global__ __launch_bounds__(128)
void build_q_k(const float* __restrict__ q, const int* __restrict__ pos,
               bf16* __restrict__ Qhh, bf16* __restrict__ Qhl, float scale)
{
    const int s = blockIdx.x, h = blockIdx.y, b = blockIdx.z;
    const float* in = q + ((size_t)(b * SS + s)) * QBOUT + h * DQ;
    const size_t ob = (((size_t)(b * NH + h) * SS) + s) * DQ;
    const int t = threadIdx.x;
    {
        const float v = in[t] * scale;
        const bf16 hh = __float2bfloat16(v);
        Qhh[ob + t] = hh;
        Qhl[ob + t] = __float2bfloat16(v - __bfloat162float(hh));
    }
    if (t < 32) {
        const float tp = (float)pos[b * SS + s];
        const float f = exp2f((float)t * (-13.2877123795494f / 32.f));
        float c, sn; sincosf(tp * f, &sn, &c);
        const float x0 = in[DNOPE + 2 * t];
        const float x1 = in[DNOPE + 2 * t + 1];
        const float v0 = (x0 * c - x1 * sn) * scale;
        const float v1 = (x1 * c + x0 * sn) * scale;
        bf16 h0 = __float2bfloat16(v0), h1 = __float2bfloat16(v1);
        Qhh[ob + DNOPE + t]      = h0;
        Qhl[ob + DNOPE + t]      = __float2bfloat16(v0 - __bfloat162float(h0));
        Qhh[ob + DNOPE + 32 + t] = h1;
        Qhl[ob + DNOPE + 32 + t] = __float2bfloat16(v1 - __bfloat162float(h1));
    }
}

// ------- build K,V -> bf16 hi/lo [b,h,s,*] (ckv = g_c1 + QRANK, stride W1R) -------
__global__ __launch_bounds__(256)
void build_kv_k(const float* __restrict__ ckv, const float* __restrict__ kv,
                const int* __restrict__ pos,
                bf16* __restrict__ Khh, bf16* __restrict__ Khl,
                bf16* __restrict__ Vhh, bf16* __restrict__ Vhl)
{
    const int s = blockIdx.x, b = blockIdx.y;
    const size_t bs = (size_t)b * SS + s;
    __shared__ float kr[DROPE];
    const int tid = threadIdx.x;
    if (tid < 32) {
        const float tp = (float)pos[bs];
        const float f = exp2f((float)tid * (-13.2877123795494f / 32.f));
        float c, sn; sincosf(tp * f, &sn, &c);
        const float x0 = ckv[bs * W1R + KVRANK + 2 * tid];
        const float x1 = ckv[bs * W1R + KVRANK + 2 * tid + 1];
        kr[tid]      = x0 * c - x1 * sn;
        kr[32 + tid] = x1 * c + x0 * sn;
    }
    __syncthreads();
    const float* kvrow = kv + bs * KVBOUT;
    for (int idx = tid; idx < NH * DQ; idx += 256) {
        const int h = idx / DQ, d = idx % DQ;
        const float v = (d < DNOPE) ? kvrow[h * (DNOPE + DV) + d] : kr[d - DNOPE];
        const size_t o = (((size_t)(b * NH + h) * SS) + s) * DQ + d;
        const bf16 hh = __float2bfloat16(v);
        Khh[o] = hh;
        Khl[o] = __float2bfloat16(v - __bfloat162float(hh));
    }
    for (int idx = tid; idx < NH * DV; idx += 256) {
        const int h = idx / DV, d = idx % DV;
        const float v = kvrow[h * (DNOPE + DV) + DNOPE + d];
        const size_t o = (((size_t)(b * NH + h) * SS) + s) * DV + d;
        const bf16 hh = __float2bfloat16(v);
        Vhh[o] = hh;
        Vhl[o] = __float2bfloat16(v - __bfloat162float(hh));
    }
}

// ====== HMMA flash attention, cp.async pipelined K (2-stage) + early V ======
#define FQM 128
#define FKN 64
#define FQH0 0                 // Q hi: 3 panels x 16384
#define FQL0 49152             // Q lo
#define FKS0 98304             // K stages: [hi 3x8192 | lo 3x8192] = 49152 each
#define FKSTG 49152
#define FVH0 196608            // V hi 16384 (64 x 256B swizzled)
#define FVL0 212992            // V lo
#define FL_SMEM 229376

__global__ __launch_bounds__(256, 1)
void flashmma_k(const bf16* __restrict__ Qhh, const bf16* __restrict__ Qhl,
                const bf16* __restrict__ Khh, const bf16* __restrict__ Khl,
                const bf16* __restrict__ Vhh, const bf16* __restrict__ Vhl,
                bf16* __restrict__ ath, bf16* __restrict__ atl)
{
    extern __shared__ char sm[];
    const uint32_t sb = s2u(sm);
    const int tid = threadIdx.x, w = tid >> 5, l = tid & 31;
    const int qt = blockIdx.x, bh = blockIdx.y;
    const int b = bh / NH, h = bh % NH;
    const int q0 = qt * FQM;

    // prologue: prefetch K tile 0 into stage 0
    {
        const uint4* Kh4 = reinterpret_cast<const uint4*>(Khh + (size_t)bh * SS * DQ);
        const uint4* Kl4 = reinterpret_cast<const uint4*>(Khl + (size_t)bh * SS * DQ);
        for (int idx = tid; idx < 64 * 24; idx += 256) {
            const int row = idx / 24, u = idx % 24;
            const int p = u >> 3, qd = u & 7;
            const uint32_t off = (uint32_t)(p * 8192) + SWZ128((uint32_t)(row * 128 + qd * 16));
            cpa16(sb + FKS0 + off,         Kh4 + row * 24 + u);
            cpa16(sb + FKS0 + 24576 + off, Kl4 + row * 24 + u);
        }
        CPA_COMMIT();
    }

    // Q tile -> smem
    {
        const uint4* Qh4 = reinterpret_cast<const uint4*>(Qhh + ((size_t)bh * SS + q0) * DQ);
        const uint4* Ql4 = reinterpret_cast<const uint4*>(Qhl + ((size_t)bh * SS + q0) * DQ);
        for (int idx = tid; idx < 128 * 24; idx += 256) {
            const int row = idx / 24, u = idx % 24;
            const int p = u >> 3, qd = u & 7;
            const uint32_t off = (uint32_t)(p * 16384) + SWZ128((uint32_t)(row * 128 + qd * 16));
            *reinterpret_cast<uint4*>(sm + FQH0 + off) = Qh4[row * 24 + u];
            *reinterpret_cast<uint4*>(sm + FQL0 + off) = Ql4[row * 24 + u];
        }
    }

    float oacc[16][4];
    #pragma unroll
    for (int i = 0; i < 16; i++)
        #pragma unroll
        for (int e = 0; e < 4; e++) oacc[i][e] = 0.f;
    float mrow[2] = {-1e30f, -1e30f};
    float lsum[2] = {0.f, 0.f};

    const int r0 = q0 + w * 16 + (l >> 2);
    const int r1 = r0 + 8;

    const int ktmax = 2 * qt + 1;
    for (int kt = 0; kt <= ktmax; kt++) {
        const int k0 = kt * FKN;
        const uint32_t kcur = sb + FKS0 + (uint32_t)(kt & 1) * FKSTG;

        {
            const uint4* Vh4 = reinterpret_cast<const uint4*>(Vhh + ((size_t)bh * SS + k0) * DV);
            const uint4* Vl4 = reinterpret_cast<const uint4*>(Vhl + ((size_t)bh * SS + k0) * DV);
            for (int idx = tid; idx < 64 * 16; idx += 256) {
                const int row = idx >> 4, qd = idx & 15;
                const uint32_t off = SWZV((uint32_t)(row * 256 + qd * 16));
                cpa16(sb + FVH0 + off, Vh4 + row * 16 + qd);
                cpa16(sb + FVL0 + off, Vl4 + row * 16 + qd);
            }
            if (kt < ktmax) {
                const uint32_t knxt = sb + FKS0 + (uint32_t)((kt + 1) & 1) * FKSTG;
                const uint4* Kh4 = reinterpret_cast<const uint4*>(Khh + ((size_t)bh * SS + k0 + FKN) * DQ);
                const uint4* Kl4 = reinterpret_cast<const uint4*>(Khl + ((size_t)bh * SS + k0 + FKN) * DQ);
                for (int idx = tid; idx < 64 * 24; idx += 256) {
                    const int row = idx / 24, u = idx % 24;
                    const int p = u >> 3, qd = u & 7;
                    const uint32_t off = (uint32_t)(p * 8192) + SWZ128((uint32_t)(row * 128 + qd * 16));
                    cpa16(knxt + off,         Kh4 + row * 24 + u);
                    cpa16(knxt + 24576 + off, Kl4 + row * 24 + u);
                }
            }
            CPA_COMMIT();
        }
        CPA_WAIT1();
        __syncthreads();

        float sacc[8][4];
        #pragma unroll
        for (int nt = 0; nt < 8; nt++)
            #pragma unroll
            for (int e = 0; e < 4; e++) sacc[nt][e] = 0.f;

        #pragma unroll
        for (int p = 0; p < 3; p++)
            #pragma unroll
            for (int ks = 0; ks < 4; ks++) {
                uint32_t ah[4], al[4];
                const uint32_t aoff = (uint32_t)(p * 16384) +
                    SWZ128((uint32_t)((w * 16 + (l & 15)) * 128 + (ks * 2 + (l >> 4)) * 16));
                ldmx4(ah, sb + FQH0 + aoff);
                ldmx4(al, sb + FQL0 + aoff);
                #pragma unroll
                for (int nt = 0; nt < 8; nt++) {
                    uint32_t bh_[2], bl_[2];
                    const uint32_t boff = (uint32_t)(p * 8192) +
                        SWZ128((uint32_t)((nt * 8 + (l & 7)) * 128 + (ks * 2 + ((l >> 3) & 1)) * 16));
                    ldmx2(bh_, kcur + boff);
                    ldmx2(bl_, kcur + 24576 + boff);
                    mma16816(sacc[nt], ah, bh_);
                    mma16816(sacc[nt], ah, bl_);
                    mma16816(sacc[nt], al, bh_);
                }
            }

        if (kt >= 2 * qt) {
            #pragma unroll
            for (int nt = 0; nt < 8; nt++) {
                const int c0 = k0 + nt * 8 + (l & 3) * 2;
                if (c0     > r0) sacc[nt][0] = -1e30f;
                if (c0 + 1 > r0) sacc[nt][1] = -1e30f;
                if (c0     > r1) sacc[nt][2] = -1e30f;
                if (c0 + 1 > r1) sacc[nt][3] = -1e30f;
            }
        }

        float alpha[2];
        #pragma unroll
        for (int sub = 0; sub < 2; sub++) {
            float tm = -1e30f;
            #pragma unroll
            for (int nt = 0; nt < 8; nt++)
                tm = fmaxf(tm, fmaxf(sacc[nt][2 * sub], sacc[nt][2 * sub + 1]));
            tm = fmaxf(tm, __shfl_xor_sync(0xffffffffu, tm, 1));
            tm = fmaxf(tm, __shfl_xor_sync(0xffffffffu, tm, 2));
            const float mn = fmaxf(mrow[sub], tm);
            alpha[sub] = __expf(mrow[sub] - mn);
            float rs = 0.f;
            #pragma unroll
            for (int nt = 0; nt < 8; nt++) {
                sacc[nt][2 * sub]     = __expf(sacc[nt][2 * sub] - mn);
                sacc[nt][2 * sub + 1] = __expf(sacc[nt][2 * sub + 1] - mn);
                rs += sacc[nt][2 * sub] + sacc[nt][2 * sub + 1];
            }
            rs += __shfl_xor_sync(0xffffffffu, rs, 1);
            rs += __shfl_xor_sync(0xffffffffu, rs, 2);
            lsum[sub] = lsum[sub] * alpha[sub] + rs;
            mrow[sub] = mn;
        }
        #pragma unroll
        for (int ntv = 0; ntv < 16; ntv++) {
            oacc[ntv][0] *= alpha[0]; oacc[ntv][1] *= alpha[0];
            oacc[ntv][2] *= alpha[1]; oacc[ntv][3] *= alpha[1];
        }

        CPA_WAIT0();
        __syncthreads();

        #pragma unroll
        for (int kt4 = 0; kt4 < 4; kt4++) {
            uint32_t pah[4], pal[4];
            {
                const float* s0 = sacc[2 * kt4];
                const float* s1 = sacc[2 * kt4 + 1];
                float h00 = __bfloat162float(__float2bfloat16(s0[0]));
                float h01 = __bfloat162float(__float2bfloat16(s0[1]));
                float h02 = __bfloat162float(__float2bfloat16(s0[2]));
                float h03 = __bfloat162float(__float2bfloat16(s0[3]));
                float h10 = __bfloat162float(__float2bfloat16(s1[0]));
                float h11 = __bfloat162float(__float2bfloat16(s1[1]));
                float h12 = __bfloat162float(__float2bfloat16(s1[2]));
                float h13 = __bfloat162float(__float2bfloat16(s1[3]));
                pah[0] = packbf2(h00, h01); pah[1] = packbf2(h02, h03);
                pah[2] = packbf2(h10, h11); pah[3] = packbf2(h12, h13);
                pal[0] = packbf2(s0[0] - h00, s0[1] - h01);
                pal[1] = packbf2(s0[2] - h02, s0[3] - h03);
                pal[2] = packbf2(s1[0] - h10, s1[1] - h11);
                pal[3] = packbf2(s1[2] - h12, s1[3] - h13);
            }
            #pragma unroll
            for (int ntv = 0; ntv < 16; ntv++) {
                uint32_t bvh[2], bvl[2];
                const uint32_t voff =
                    SWZV((uint32_t)((kt4 * 16 + (l & 7) + ((l >> 3) & 1) * 8) * 256 + ntv * 16));
                ldmx2t(bvh, sb + FVH0 + voff);
                ldmx2t(bvl, sb + FVL0 + voff);
                mma16816(oacc[ntv], pah, bvh);
                mma16816(oacc[ntv], pah, bvl);
                mma16816(oacc[ntv], pal, bvh);
            }
        }
        __syncthreads();
    }

    const float inv0 = 1.f / lsum[0];
    const float inv1 = 1.f / lsum[1];
    const size_t row0 = (size_t)(b * SS + r0) * ODIM + h * DV;
    const size_t row1 = (size_t)(b * SS + r1) * ODIM + h * DV;
    #pragma unroll
    for (int ntv = 0; ntv < 16; ntv++) {
        const int col = ntv * 8 + (l & 3) * 2;
        const float v00 = oacc[ntv][0] * inv0, v01 = oacc[ntv][1] * inv0;
        const float v10 = oacc[ntv][2] * inv1, v11 = oacc[ntv][3] * inv1;
        float h00 = __bfloat162float(__float2bfloat16(v00));
        float h01 = __bfloat162float(__float2bfloat16(v01));
        float h10 = __bfloat162float(__float2bfloat16(v10));
        float h11 = __bfloat162float(__float2bfloat16(v11));
        *reinterpret_cast<uint32_t*>(&ath[row0 + col]) = packbf2(h00, h01);
        *reinterpret_cast<uint32_t*>(&atl[row0 + col]) = packbf2(v00 - h00, v01 - h01);
        *reinterpret_cast<uint32_t*>(&ath[row1 + col]) = packbf2(h10, h11);
        *reinterpret_cast<uint32_t*>(&atl[row1 + col]) = packbf2(v10 - h10, v11 - h11);
    }
}

// ---------------- launch ----------------
extern "C" void kernel_launch(void* const* d_in, const int* in_sizes, int n_in,
                              void* d_out, int out_size)
{
    const float* hidden = (const float*)d_in[0];
    const float* qaw    = (const float*)d_in[1];
    const float* qaln   = (const float*)d_in[2];
    const float* qbw    = (const float*)d_in[3];
    const float* kvaw   = (const float*)d_in[4];
    const float* kvaln  = (const float*)d_in[5];
    const float* kvbw   = (const float*)d_in[6];
    const float* ow     = (const float*)d_in[7];
    const int*   pos    = (const int*)d_in[8];
    // d_in[9] = attention_mask (causal tril) — enforced analytically in flash kernel
    float* out = (float*)d_out;

    float *c1, *q, *kv;
    bf16 *hidh, *hidl, *w1h, *w1l, *qbwh, *qbwl, *kvbwh, *kvbwl;
    bf16 *owh, *owl, *qch, *qcl, *cnh, *cnl, *ath, *atl;
    bf16 *Qhh, *Qhl, *Khh, *Khl, *Vhh, *Vhl;
    cudaGetSymbolAddress((void**)&c1,  g_c1);   cudaGetSymbolAddress((void**)&q,    g_q);
    cudaGetSymbolAddress((void**)&kv,  g_kv);
    cudaGetSymbolAddress((void**)&hidh, g_hidh); cudaGetSymbolAddress((void**)&hidl, g_hidl);
    cudaGetSymbolAddress((void**)&w1h, g_w1h);   cudaGetSymbolAddress((void**)&w1l, g_w1l);
    cudaGetSymbolAddress((void**)&qbwh, g_qbwh); cudaGetSymbolAddress((void**)&qbwl, g_qbwl);
    cudaGetSymbolAddress((void**)&kvbwh, g_kvbwh); cudaGetSymbolAddress((void**)&kvbwl, g_kvbwl);
    cudaGetSymbolAddress((void**)&owh, g_owh);   cudaGetSymbolAddress((void**)&owl, g_owl);
    cudaGetSymbolAddress((void**)&qch, g_qch);   cudaGetSymbolAddress((void**)&qcl, g_qcl);
    cudaGetSymbolAddress((void**)&cnh, g_cnh);   cudaGetSymbolAddress((void**)&cnl, g_cnl);
    cudaGetSymbolAddress((void**)&ath, g_ath);   cudaGetSymbolAddress((void**)&atl, g_atl);
    cudaGetSymbolAddress((void**)&Qhh, g_Qhh);   cudaGetSymbolAddress((void**)&Qhl, g_Qhl);
    cudaGetSymbolAddress((void**)&Khh, g_Khh);   cudaGetSymbolAddress((void**)&Khl, g_Khl);
    cudaGetSymbolAddress((void**)&Vhh, g_Vhh);   cudaGetSymbolAddress((void**)&Vhl, g_Vhl);

    cudaFuncSetAttribute(gemm_tc,    cudaFuncAttributeMaxDynamicSharedMemorySize, GEMM_SMEM);
    cudaFuncSetAttribute(flashmma_k, cudaFuncAttributeMaxDynamicSharedMemorySize, FL_SMEM);

    #define CVT(x, h, l, n) cvt_pair_k<<<(unsigned)(((size_t)(n) + 255) / 256), 256>>>(x, h, l, (size_t)(n))
    CVT(hidden, hidh, hidl, (size_t)MTOK * HID);
    CVT(qaw,    w1h,  w1l,  (size_t)QRANK * HID);            // rows [0, 1536)
    cvt_pad_k<<<(unsigned)(((size_t)KVAPAD * HID + 255) / 256), 256>>>(
        kvaw, w1h + (size_t)QRANK * HID, w1l + (size_t)QRANK * HID,
        KVAOUT, HID, KVAPAD);                                 // rows [1536, 2176)
    CVT(qbw,    qbwh, qbwl, (size_t)QBOUT * QRANK);
    CVT(kvbw,   kvbwh, kvbwl, (size_t)KVBOUT * KVRANK);
    CVT(ow,     owh,  owl,  (size_t)HID * ODIM);

    // 1) combined [q_c | ckv] = hidden @ [q_a ; kv_a]^T   [4096, 2176]
    gemm_tc<<<dim3(W1R/TN, MTOK/TM), 256, GEMM_SMEM>>>(hidh, hidl, w1h, w1l, c1, HID, W1R);
    // 2) rmsnorm(q_c) and rmsnorm(ckv[:, :512])
    rmsnorm_pair_k<<<MTOK, 256>>>(c1, qaln, qch, qcl, QRANK, W1R);
    rmsnorm_pair_k<<<MTOK, 256>>>(c1 + QRANK, kvaln, cnh, cnl, KVRANK, W1R);
    // 3) q = qcn @ q_b^T
    gemm_tc<<<dim3(QBOUT/TN, MTOK/TM), 256, GEMM_SMEM>>>(qch, qcl, qbwh, qbwl, q, QRANK, QBOUT);
    // 4) kv = cn @ kv_b^T
    gemm_tc<<<dim3(KVBOUT/TN, MTOK/TM), 256, GEMM_SMEM>>>(cnh, cnl, kvbwh, kvbwl, kv, KVRANK, KVBOUT);
    // 5) build bf16 split Q (rope+scale) and K,V
    build_q_k<<<dim3(SS, NH, BB), 128>>>(q, pos, Qhh, Qhl, rsqrtf((float)DQ));
    build_kv_k<<<dim3(SS, BB), 256>>>(c1 + QRANK, kv, pos, Khh, Khl, Vhh, Vhl);
    // 6) HMMA flash attention -> attn (hi,lo) bf16
    flashmma_k<<<dim3(SS/FQM, BB*NH), 256, FL_SMEM>>>(Qhh, Qhl, Khh, Khl, Vhh, Vhl, ath, atl);
    // 7) out = attn @ o^T
    gemm_tc<<<dim3(HID/TN, MTOK/TM), 256, GEMM_SMEM>>>(ath, atl, owh, owl, out, ODIM, HID);
}

// round 15
// speedup vs baseline: 1.5503x; 1.5503x over previous
#include <cuda_runtime.h>
#include <cuda_bf16.h>
#include <math.h>
#include <stdint.h>

// ---------------- problem constants ----------------
#define BB 2
#define SS 2048
#define HID 5120
#define NH 32
#define DNOPE 128
#define DROPE 64
#define DV 128
#define DQ 192
#define QRANK 1536
#define KVRANK 512
#define MTOK (BB*SS)            // 4096
#define KVAOUT (KVRANK+DROPE)   // 576
#define KVAPAD 640              // kv_a rows padded to /128
#define W1R (QRANK+KVAPAD)      // 2176 combined q_a+kv_a output dim
#define QBOUT (NH*DQ)           // 6144
#define KVBOUT (NH*(DNOPE+DV))  // 8192
#define ODIM  (NH*DV)           // 4096

typedef __nv_bfloat16 bf16;

// ---------------- scratch (static device, allocation-free) ----------------
__device__ float g_c1  [(size_t)MTOK*W1R];     // [q_c | ckv] combined
__device__ float g_q   [(size_t)MTOK*QBOUT];
__device__ float g_kv  [(size_t)MTOK*KVBOUT];
// bf16 hi/lo operand buffers (projections)
__device__ bf16 g_hidh[(size_t)MTOK*HID],   g_hidl[(size_t)MTOK*HID];
__device__ bf16 g_w1h [(size_t)W1R*HID],    g_w1l [(size_t)W1R*HID];   // [qaw ; kvaw(pad)]
__device__ bf16 g_qbwh[(size_t)QBOUT*QRANK],g_qbwl[(size_t)QBOUT*QRANK];
__device__ bf16 g_kvbwh[(size_t)KVBOUT*KVRANK], g_kvbwl[(size_t)KVBOUT*KVRANK];
__device__ bf16 g_owh [(size_t)HID*ODIM],   g_owl [(size_t)HID*ODIM];
__device__ bf16 g_qch [(size_t)MTOK*QRANK], g_qcl [(size_t)MTOK*QRANK];
__device__ bf16 g_cnh [(size_t)MTOK*KVRANK],g_cnl [(size_t)MTOK*KVRANK];
__device__ bf16 g_ath [(size_t)MTOK*ODIM],  g_atl [(size_t)MTOK*ODIM];
// bf16 hi/lo attention operands [b,h][s][*]
__device__ bf16 g_Qhh[(size_t)BB*NH*SS*DQ], g_Qhl[(size_t)BB*NH*SS*DQ];
__device__ bf16 g_Khh[(size_t)BB*NH*SS*DQ], g_Khl[(size_t)BB*NH*SS*DQ];
__device__ bf16 g_Vhh[(size_t)BB*NH*SS*DV], g_Vhl[(size_t)BB*NH*SS*DV];

// ---------------- warp-MMA helpers (plain sm_103-legal PTX) ----------------
__device__ __forceinline__ uint32_t s2u(const void* p) {
    uint32_t a;
    asm("{ .reg .u64 t; cvta.to.shared.u64 t, %1; cvt.u32.u64 %0, t; }" : "=r"(a) : "l"(p));
    return a;
}
#define SWZ128(off) ((off) ^ (((off) >> 3) & 0x70))   // 128B-row panels
#define SWZV(off)   ((off) ^ (((off) >> 4) & 0x70))   // 256B-row V panel

__device__ __forceinline__ void ldmx4(uint32_t r[4], uint32_t a) {
    asm volatile("ldmatrix.sync.aligned.m8n8.x4.shared.b16 {%0,%1,%2,%3}, [%4];"
        : "=r"(r[0]), "=r"(r[1]), "=r"(r[2]), "=r"(r[3]) : "r"(a));
}
__device__ __forceinline__ void ldmx2(uint32_t r[2], uint32_t a) {
    asm volatile("ldmatrix.sync.aligned.m8n8.x2.shared.b16 {%0,%1}, [%2];"
        : "=r"(r[0]), "=r"(r[1]) : "r"(a));
}
__device__ __forceinline__ void ldmx2t(uint32_t r[2], uint32_t a) {
    asm volatile("ldmatrix.sync.aligned.m8n8.x2.trans.shared.b16 {%0,%1}, [%2];"
        : "=r"(r[0]), "=r"(r[1]) : "r"(a));
}
__device__ __forceinline__ void mma16816(float c[4], const uint32_t a[4], const uint32_t b[2]) {
    asm volatile(
        "mma.sync.aligned.m16n8k16.row.col.f32.bf16.bf16.f32 "
        "{%0,%1,%2,%3}, {%4,%5,%6,%7}, {%8,%9}, {%0,%1,%2,%3};"
        : "+f"(c[0]), "+f"(c[1]), "+f"(c[2]), "+f"(c[3])
        : "r"(a[0]), "r"(a[1]), "r"(a[2]), "r"(a[3]), "r"(b[0]), "r"(b[1]));
}
__device__ __forceinline__ uint32_t packbf2(float lo, float hi) {
    __nv_bfloat162 t = __floats2bfloat162_rn(lo, hi);
    return *reinterpret_cast<uint32_t*>(&t);
}
__device__ __forceinline__ void cpa16(uint32_t dst, const void* src) {
    asm volatile("cp.async.cg.shared.global [%0], [%1], 16;" :: "r"(dst), "l"(src));
}
#define CPA_COMMIT() asm volatile("cp.async.commit_group;" ::: "memory")
#define CPA_WAIT1()  asm volatile("cp.async.wait_group 1;" ::: "memory")
#define CPA_WAIT0()  asm volatile("cp.async.wait_group 0;" ::: "memory")

// ===== split-bf16 HMMA GEMM, 128x128 tile, 2-stage cp.async, 1 barrier/chunk =====
// (round-12 proven configuration, verbatim)
#define TM 128
#define TN 128
#define TKC 64
#define SM_AH 0
#define SM_AL 16384
#define SM_BH 32768
#define SM_BL 49152
#define STG_B 65536
#define GEMM_SMEM (2 * STG_B)   // 131072

__global__ __launch_bounds__(256, 1)
void gemm_tc(const bf16* __restrict__ Ah, const bf16* __restrict__ Al,
             const bf16* __restrict__ Bh, const bf16* __restrict__ Bl,
             float* __restrict__ C, int K, int ldc)
{
    extern __shared__ char smem[];
    const uint32_t sb = s2u(smem);
    const int tid = threadIdx.x, wid = tid >> 5, lid = tid & 31;
    const int m0 = blockIdx.y * TM, n0 = blockIdx.x * TN;
    const int wm = wid & 1, wn = wid >> 1;

    const int grow = tid >> 1;
    const int half = tid & 1;
    const uint4* rAh = reinterpret_cast<const uint4*>(Ah + (size_t)(m0 + grow) * K);
    const uint4* rAl = reinterpret_cast<const uint4*>(Al + (size_t)(m0 + grow) * K);
    const uint4* rBh = reinterpret_cast<const uint4*>(Bh + (size_t)(n0 + grow) * K);
    const uint4* rBl = reinterpret_cast<const uint4*>(Bl + (size_t)(n0 + grow) * K);

    uint32_t soff[4];
    #pragma unroll
    for (int j = 0; j < 4; j++)
        soff[j] = SWZ128((uint32_t)(grow * 128 + half * 64 + j * 16));

    float c[4][4][4];
    #pragma unroll
    for (int mt = 0; mt < 4; mt++)
        #pragma unroll
        for (int nt = 0; nt < 4; nt++)
            #pragma unroll
            for (int e = 0; e < 4; e++) c[mt][nt][e] = 0.f;

    const int arow = wm * 64 + (lid & 15);
    const int aq   = lid >> 4;
    const int brow = wn * 32 + (lid & 7);
    const int bq   = (lid >> 3) & 1;

    // prologue: chunk 0 -> stage 0
    {
        const int base = half * 4;
        #pragma unroll
        for (int j = 0; j < 4; j++) {
            cpa16(sb + SM_AH + soff[j], rAh + base + j);
            cpa16(sb + SM_AL + soff[j], rAl + base + j);
            cpa16(sb + SM_BH + soff[j], rBh + base + j);
            cpa16(sb + SM_BL + soff[j], rBl + base + j);
        }
        CPA_COMMIT();
    }

    const int nch = K / TKC;
    for (int ch = 0; ch < nch; ch++) {
        const uint32_t scur = sb + (uint32_t)(ch & 1) * STG_B;
        CPA_WAIT0();
        __syncthreads();
        if (ch + 1 < nch) {
            const uint32_t snxt = sb + (uint32_t)((ch + 1) & 1) * STG_B;
            const int base = (ch + 1) * (TKC / 8) + half * 4;
            #pragma unroll
            for (int j = 0; j < 4; j++) {
                cpa16(snxt + SM_AH + soff[j], rAh + base + j);
                cpa16(snxt + SM_AL + soff[j], rAl + base + j);
                cpa16(snxt + SM_BH + soff[j], rBh + base + j);
                cpa16(snxt + SM_BL + soff[j], rBl + base + j);
            }
            CPA_COMMIT();
        }

        #pragma unroll
        for (int ks = 0; ks < 4; ks++) {
            uint32_t ah[4][4], al[4][4], bh[4][2], bl[4][2];
            #pragma unroll
            for (int mt = 0; mt < 4; mt++) {
                const uint32_t off = SWZ128((uint32_t)((arow + mt * 16) * 128 + (ks * 2 + aq) * 16));
                ldmx4(ah[mt], scur + SM_AH + off);
                ldmx4(al[mt], scur + SM_AL + off);
            }
            #pragma unroll
            for (int nt = 0; nt < 4; nt++) {
                const uint32_t off = SWZ128((uint32_t)((brow + nt * 8) * 128 + (ks * 2 + bq) * 16));
                ldmx2(bh[nt], scur + SM_BH + off);
                ldmx2(bl[nt], scur + SM_BL + off);
            }
            #pragma unroll
            for (int mt = 0; mt < 4; mt++)
                #pragma unroll
                for (int nt = 0; nt < 4; nt++) {
                    mma16816(c[mt][nt], ah[mt], bh[nt]);
                    mma16816(c[mt][nt], ah[mt], bl[nt]);
                    mma16816(c[mt][nt], al[mt], bh[nt]);
                }
        }
    }

    const int mbase = m0 + wm * 64 + (lid >> 2);
    const int nbase = n0 + wn * 32 + (lid & 3) * 2;
    #pragma unroll
    for (int mt = 0; mt < 4; mt++)
        #pragma unroll
        for (int nt = 0; nt < 4; nt++) {
            float* p0 = C + (size_t)(mbase + mt * 16) * ldc + nbase + nt * 8;
            float* p1 = p0 + 8 * ldc;
            *reinterpret_cast<float2*>(p0) = make_float2(c[mt][nt][0], c[mt][nt][1]);
            *reinterpret_cast<float2*>(p1) = make_float2(c[mt][nt][2], c[mt][nt][3]);
        }
}

// ------- fp32 -> (hi,lo) bf16, vectorized 4 elems/thread -------
__global__ __launch_bounds__(256)
void cvt_pair4_k(const float* __restrict__ x, bf16* __restrict__ h,
                 bf16* __restrict__ l, size_t n4)
{
    const size_t i = (size_t)blockIdx.x * 256 + threadIdx.x;
    if (i >= n4) return;
    const float4 v = reinterpret_cast<const float4*>(x)[i];
    const float h0 = __bfloat162float(__float2bfloat16(v.x));
    const float h1 = __bfloat162float(__float2bfloat16(v.y));
    const float h2 = __bfloat162float(__float2bfloat16(v.z));
    const float h3 = __bfloat162float(__float2bfloat16(v.w));
    uint2 hp, lp;
    hp.x = packbf2(h0, h1);          hp.y = packbf2(h2, h3);
    lp.x = packbf2(v.x - h0, v.y - h1); lp.y = packbf2(v.z - h2, v.w - h3);
    reinterpret_cast<uint2*>(h)[i] = hp;
    reinterpret_cast<uint2*>(l)[i] = lp;
}

// pad rows [rows, padrows) with zeros; cols % 4 == 0 so groups never straddle rows
__global__ __launch_bounds__(256)
void cvt_pad4_k(const float* __restrict__ x, bf16* __restrict__ h,
                bf16* __restrict__ l, int rows, int cols, int padrows)
{
    const size_t i = (size_t)blockIdx.x * 256 + threadIdx.x;
    if (i >= (size_t)padrows * (cols / 4)) return;
    const int r = (int)(i / (cols / 4));
    uint2 hp, lp;
    if (r < rows) {
        const float4 v = reinterpret_cast<const float4*>(x)[i];
        const float h0 = __bfloat162float(__float2bfloat16(v.x));
        const float h1 = __bfloat162float(__float2bfloat16(v.y));
        const float h2 = __bfloat162float(__float2bfloat16(v.z));
        const float h3 = __bfloat162float(__float2bfloat16(v.w));
        hp.x = packbf2(h0, h1);          hp.y = packbf2(h2, h3);
        lp.x = packbf2(v.x - h0, v.y - h1); lp.y = packbf2(v.z - h2, v.w - h3);
    } else {
        hp.x = hp.y = lp.x = lp.y = 0u;
    }
    reinterpret_cast<uint2*>(h)[i] = hp;
    reinterpret_cast<uint2*>(l)[i] = lp;
}

// ---------------- RMSNorm -> (hi,lo) bf16 ----------------
__global__ __launch_bounds__(256)
void rmsnorm_pair_k(const float* __restrict__ x, const float* __restrict__ w,
                    bf16* __restrict__ yh, bf16* __restrict__ yl,
                    int n, int in_stride)
{
    const int row = blockIdx.x;
    const float* xr = x + (size_t)row * in_stride;
    bf16* yhr = yh + (size_t)row * n;
    bf16* ylr = yl + (size_t)row * n;
    __shared__ float red[256];
    float s = 0.f;
    for (int i = threadIdx.x; i < n; i += 256) { float v = xr[i]; s += v * v; }
    red[threadIdx.x] = s; __syncthreads();
    for (int o = 128; o; o >>= 1) {
        if (threadIdx.x < o) red[threadIdx.x] += red[threadIdx.x + o];
        __syncthreads();
    }
    const float r = rsqrtf(red[0] / n + 1e-6f);
    for (int i = threadIdx.x; i < n; i += 256) {
        const float v = xr[i] * r * w[i];
        const bf16 hh = __float2bfloat16(v);
        yhr[i] = hh;
        ylr[i] = __float2bfloat16(v - __bfloat162float(hh));
    }
}

// ------- build Q (RoPE + scale) -> bf16 hi/lo [b,h,s,192] -------
__global__ __launch_bounds__(128)
void build_q_k(const float* __restrict__ q, const int* __restrict__ pos,
               bf16* __restrict__ Qhh, bf16* __restrict__ Qhl, float scale)
{
    const int s = blockIdx.x, h = blockIdx.y, b = blockIdx.z;
    const float* in = q + ((size_t)(b * SS + s)) * QBOUT + h * DQ;
    const size_t ob = (((size_t)(b * NH + h) * SS) + s) * DQ;
    const int t = threadIdx.x;
    {
        const float v = in[t] * scale;
        const bf16 hh = __float2bfloat16(v);
        Qhh[ob + t] = hh;
        Qhl[ob + t] = __float2bfloat16(v - __bfloat162float(hh));
    }
    if (t < 32) {
        const float tp = (float)pos[b * SS + s];
        const float f = exp2f((float)t * (-13.2877123795494f / 32.f));
        float c, sn; sincosf(tp * f, &sn, &c);
        const float x0 = in[DNOPE + 2 * t];
        const float x1 = in[DNOPE + 2 * t + 1];
        const float v0 = (x0 * c - x1 * sn) * scale;
        const float v1 = (x1 * c + x0 * sn) * scale;
        bf16 h0 = __float2bfloat16(v0), h1 = __float2bfloat16(v1);
        Qhh[ob + DNOPE + t]      = h0;
        Qhl[ob + DNOPE + t]      = __float2bfloat16(v0 - __bfloat162float(h0));
        Qhh[ob + DNOPE + 32 + t] = h1;
        Qhl[ob + DNOPE + 32 + t] = __float2bfloat16(v1 - __bfloat162float(h1));
    }
}

// ------- build K,V -> bf16 hi/lo [b,h,s,*] (ckv = g_c1 + QRANK, stride W1R) -------
__global__ __launch_bounds__(256)
void build_kv_k(const float* __restrict__ ckv, const float* __restrict__ kv,
                const int* __restrict__ pos,
                bf16* __restrict__ Khh, bf16* __restrict__ Khl,
                bf16* __restrict__ Vhh, bf16* __restrict__ Vhl)
{
    const int s = blockIdx.x, b = blockIdx.y;
    const size_t bs = (size_t)b * SS + s;
    __shared__ float kr[DROPE];
    const int tid = threadIdx.x;
    if (tid < 32) {
        const float tp = (float)pos[bs];
        const float f = exp2f((float)tid * (-13.2877123795494f / 32.f));
        float c, sn; sincosf(tp * f, &sn, &c);
        const float x0 = ckv[bs * W1R + KVRANK + 2 * tid];
        const float x1 = ckv[bs * W1R + KVRANK + 2 * tid + 1];
        kr[tid]      = x0 * c - x1 * sn;
        kr[32 + tid] = x1 * c + x0 * sn;
    }
    __syncthreads();
    const float* kvrow = kv + bs * KVBOUT;
    for (int idx = tid; idx < NH * DQ; idx += 256) {
        const int h = idx / DQ, d = idx % DQ;
        const float v = (d < DNOPE) ? kvrow[h * (DNOPE + DV) + d] : kr[d - DNOPE];
        const size_t o = (((size_t)(b * NH + h) * SS) + s) * DQ + d;
        const bf16 hh = __float2bfloat16(v);
        Khh[o] = hh;
        Khl[o] = __float2bfloat16(v - __bfloat162float(hh));
    }
    for (int idx = tid; idx < NH * DV; idx += 256) {
        const int h = idx / DV, d = idx % DV;
        const float v = kvrow[h * (DNOPE + DV) + DNOPE + d];
        const size_t o = (((size_t)(b * NH + h) * SS) + s) * DV + d;
        const bf16 hh = __float2bfloat16(v);
        Vhh[o] = hh;
        Vhl[o] = __float2bfloat16(v - __bfloat162float(hh));
    }
}

// ====== HMMA flash attention, cp.async pipelined K (2-stage) + early V ======
// (round-12 proven configuration, verbatim)
#define FQM 128
#define FKN 64
#define FQH0 0
#define FQL0 49152
#define FKS0 98304
#define FKSTG 49152
#define FVH0 196608
#define FVL0 212992
#define FL_SMEM 229376

__global__ __launch_bounds__(256, 1)
void flashmma_k(const bf16* __restrict__ Qhh, const bf16* __restrict__ Qhl,
                const bf16* __restrict__ Khh, const bf16* __restrict__ Khl,
                const bf16* __restrict__ Vhh, const bf16* __restrict__ Vhl,
                bf16* __restrict__ ath, bf16* __restrict__ atl)
{
    extern __shared__ char sm[];
    const uint32_t sb = s2u(sm);
    const int tid = threadIdx.x, w = tid >> 5, l = tid & 31;
    const int qt = blockIdx.x, bh = blockIdx.y;
    const int b = bh / NH, h = bh % NH;
    const int q0 = qt * FQM;

    {
        const uint4* Kh4 = reinterpret_cast<const uint4*>(Khh + (size_t)bh * SS * DQ);
        const uint4* Kl4 = reinterpret_cast<const uint4*>(Khl + (size_t)bh * SS * DQ);
        for (int idx = tid; idx < 64 * 24; idx += 256) {
            const int row = idx / 24, u = idx % 24;
            const int p = u >> 3, qd = u & 7;
            const uint32_t off = (uint32_t)(p * 8192) + SWZ128((uint32_t)(row * 128 + qd * 16));
            cpa16(sb + FKS0 + off,         Kh4 + row * 24 + u);
            cpa16(sb + FKS0 + 24576 + off, Kl4 + row * 24 + u);
        }
        CPA_COMMIT();
    }

    {
        const uint4* Qh4 = reinterpret_cast<const uint4*>(Qhh + ((size_t)bh * SS + q0) * DQ);
        const uint4* Ql4 = reinterpret_cast<const uint4*>(Qhl + ((size_t)bh * SS + q0) * DQ);
        for (int idx = tid; idx < 128 * 24; idx += 256) {
            const int row = idx / 24, u = idx % 24;
            const int p = u >> 3, qd = u & 7;
            const uint32_t off = (uint32_t)(p * 16384) + SWZ128((uint32_t)(row * 128 + qd * 16));
            *reinterpret_cast<uint4*>(sm + FQH0 + off) = Qh4[row * 24 + u];
            *reinterpret_cast<uint4*>(sm + FQL0 + off) = Ql4[row * 24 + u];
        }
    }

    float oacc[16][4];
    #pragma unroll
    for (int i = 0; i < 16; i++)
        #pragma unroll
        for (int e = 0; e < 4; e++) oacc[i][e] = 0.f;
    float mrow[2] = {-1e30f, -1e30f};
    float lsum[2] = {0.f, 0.f};

    const int r0 = q0 + w * 16 + (l >> 2);
    const int r1 = r0 + 8;

    const int ktmax = 2 * qt + 1;
    for (int kt = 0; kt <= ktmax; kt++) {
        const int k0 = kt * FKN;
        const uint32_t kcur = sb + FKS0 + (uint32_t)(kt & 1) * FKSTG;

        {
            const uint4* Vh4 = reinterpret_cast<const uint4*>(Vhh + ((size_t)bh * SS + k0) * DV);
            const uint4* Vl4 = reinterpret_cast<const uint4*>(Vhl + ((size_t)bh * SS + k0) * DV);
            for (int idx = tid; idx < 64 * 16; idx += 256) {
                const int row = idx >> 4, qd = idx & 15;
                const uint32_t off = SWZV((uint32_t)(row * 256 + qd * 16));
                cpa16(sb + FVH0 + off, Vh4 + row * 16 + qd);
                cpa16(sb + FVL0 + off, Vl4 + row * 16 + qd);
            }
            if (kt < ktmax) {
                const uint32_t knxt = sb + FKS0 + (uint32_t)((kt + 1) & 1) * FKSTG;
                const uint4* Kh4 = reinterpret_cast<const uint4*>(Khh + ((size_t)bh * SS + k0 + FKN) * DQ);
                const uint4* Kl4 = reinterpret_cast<const uint4*>(Khl + ((size_t)bh * SS + k0 + FKN) * DQ);
                for (int idx = tid; idx < 64 * 24; idx += 256) {
                    const int row = idx / 24, u = idx % 24;
                    const int p = u >> 3, qd = u & 7;
                    const uint32_t off = (uint32_t)(p * 8192) + SWZ128((uint32_t)(row * 128 + qd * 16));
                    cpa16(knxt + off,         Kh4 + row * 24 + u);
                    cpa16(knxt + 24576 + off, Kl4 + row * 24 + u);
                }
            }
            CPA_COMMIT();
        }
        CPA_WAIT1();
        __syncthreads();

        float sacc[8][4];
        #pragma unroll
        for (int nt = 0; nt < 8; nt++)
            #pragma unroll
            for (int e = 0; e < 4; e++) sacc[nt][e] = 0.f;

        #pragma unroll
        for (int p = 0; p < 3; p++)
            #pragma unroll
            for (int ks = 0; ks < 4; ks++) {
                uint32_t ah[4], al[4];
                const uint32_t aoff = (uint32_t)(p * 16384) +
                    SWZ128((uint32_t)((w * 16 + (l & 15)) * 128 + (ks * 2 + (l >> 4)) * 16));
                ldmx4(ah, sb + FQH0 + aoff);
                ldmx4(al, sb + FQL0 + aoff);
                #pragma unroll
                for (int nt = 0; nt < 8; nt++) {
                    uint32_t bh_[2], bl_[2];
                    const uint32_t boff = (uint32_t)(p * 8192) +
                        SWZ128((uint32_t)((nt * 8 + (l & 7)) * 128 + (ks * 2 + ((l >> 3) & 1)) * 16));
                    ldmx2(bh_, kcur + boff);
                    ldmx2(bl_, kcur + 24576 + boff);
                    mma16816(sacc[nt], ah, bh_);
                    mma16816(sacc[nt], ah, bl_);
                    mma16816(sacc[nt], al, bh_);
                }
            }

        if (kt >= 2 * qt) {
            #pragma unroll
            for (int nt = 0; nt < 8; nt++) {
                const int c0 = k0 + nt * 8 + (l & 3) * 2;
                if (c0     > r0) sacc[nt][0] = -1e30f;
                if (c0 + 1 > r0) sacc[nt][1] = -1e30f;
                if (c0     > r1) sacc[nt][2] = -1e30f;
                if (c0 + 1 > r1) sacc[nt][3] = -1e30f;
            }
        }

        float alpha[2];
        #pragma unroll
        for (int sub = 0; sub < 2; sub++) {
            float tm = -1e30f;
            #pragma unroll
            for (int nt = 0; nt < 8; nt++)
                tm = fmaxf(tm, fmaxf(sacc[nt][2 * sub], sacc[nt][2 * sub + 1]));
            tm = fmaxf(tm, __shfl_xor_sync(0xffffffffu, tm, 1));
            tm = fmaxf(tm, __shfl_xor_sync(0xffffffffu, tm, 2));
            const float mn = fmaxf(mrow[sub], tm);
            alpha[sub] = __expf(mrow[sub] - mn);
            float rs = 0.f;
            #pragma unroll
            for (int nt = 0; nt < 8; nt++) {
                sacc[nt][2 * sub]     = __expf(sacc[nt][2 * sub] - mn);
                sacc[nt][2 * sub + 1] = __expf(sacc[nt][2 * sub + 1] - mn);
                rs += sacc[nt][2 * sub] + sacc[nt][2 * sub + 1];
            }
            rs += __shfl_xor_sync(0xffffffffu, rs, 1);
            rs += __shfl_xor_sync(0xffffffffu, rs, 2);
            lsum[sub] = lsum[sub] * alpha[sub] + rs;
            mrow[sub] = mn;
        }
        #pragma unroll
        for (int ntv = 0; ntv < 16; ntv++) {
            oacc[ntv][0] *= alpha[0]; oacc[ntv][1] *= alpha[0];
            oacc[ntv][2] *= alpha[1]; oacc[ntv][3] *= alpha[1];
        }

        CPA_WAIT0();
        __syncthreads();

        #pragma unroll
        for (int kt4 = 0; kt4 < 4; kt4++) {
            uint32_t pah[4], pal[4];
            {
                const float* s0 = sacc[2 * kt4];
                const float* s1 = sacc[2 * kt4 + 1];
                float h00 = __bfloat162float(__float2bfloat16(s0[0]));
                float h01 = __bfloat162float(__float2bfloat16(s0[1]));
                float h02 = __bfloat162float(__float2bfloat16(s0[2]));
                float h03 = __bfloat162float(__float2bfloat16(s0[3]));
                float h10 = __bfloat162float(__float2bfloat16(s1[0]));
                float h11 = __bfloat162float(__float2bfloat16(s1[1]));
                float h12 = __bfloat162float(__float2bfloat16(s1[2]));
                float h13 = __bfloat162float(__float2bfloat16(s1[3]));
                pah[0] = packbf2(h00, h01); pah[1] = packbf2(h02, h03);
                pah[2] = packbf2(h10, h11); pah[3] = packbf2(h12, h13);
                pal[0] = packbf2(s0[0] - h00, s0[1] - h01);
                pal[1] = packbf2(s0[2] - h02, s0[3] - h03);
                pal[2] = packbf2(s1[0] - h10, s1[1] - h11);
                pal[3] = packbf2(s1[2] - h12, s1[3] - h13);
            }
            #pragma unroll
            for (int ntv = 0; ntv < 16; ntv++) {
                uint32_t bvh[2], bvl[2];
                const uint32_t voff =
                    SWZV((uint32_t)((kt4 * 16 + (l & 7) + ((l >> 3) & 1) * 8) * 256 + ntv * 16));
                ldmx2t(bvh, sb + FVH0 + voff);
                ldmx2t(bvl, sb + FVL0 + voff);
                mma16816(oacc[ntv], pah, bvh);
                mma16816(oacc[ntv], pah, bvl);
                mma16816(oacc[ntv], pal, bvh);
            }
        }
        __syncthreads();
    }

    const float inv0 = 1.f / lsum[0];
    const float inv1 = 1.f / lsum[1];
    const size_t row0 = (size_t)(b * SS + r0) * ODIM + h * DV;
    const size_t row1 = (size_t)(b * SS + r1) * ODIM + h * DV;
    #pragma unroll
    for (int ntv = 0; ntv < 16; ntv++) {
        const int col = ntv * 8 + (l & 3) * 2;
        const float v00 = oacc[ntv][0] * inv0, v01 = oacc[ntv][1] * inv0;
        const float v10 = oacc[ntv][2] * inv1, v11 = oacc[ntv][3] * inv1;
        float h00 = __bfloat162float(__float2bfloat16(v00));
        float h01 = __bfloat162float(__float2bfloat16(v01));
        float h10 = __bfloat162float(__float2bfloat16(v10));
        float h11 = __bfloat162float(__float2bfloat16(v11));
        *reinterpret_cast<uint32_t*>(&ath[row0 + col]) = packbf2(h00, h01);
        *reinterpret_cast<uint32_t*>(&atl[row0 + col]) = packbf2(v00 - h00, v01 - h01);
        *reinterpret_cast<uint32_t*>(&ath[row1 + col]) = packbf2(h10, h11);
        *reinterpret_cast<uint32_t*>(&atl[row1 + col]) = packbf2(v10 - h10, v11 - h11);
    }
}

// ---------------- launch ----------------
extern "C" void kernel_launch(void* const* d_in, const int* in_sizes, int n_in,
                              void* d_out, int out_size)
{
    const float* hidden = (const float*)d_in[0];
    const float* qaw    = (const float*)d_in[1];
    const float* qaln   = (const float*)d_in[2];
    const float* qbw    = (const float*)d_in[3];
    const float* kvaw   = (const float*)d_in[4];
    const float* kvaln  = (const float*)d_in[5];
    const float* kvbw   = (const float*)d_in[6];
    const float* ow     = (const float*)d_in[7];
    const int*   pos    = (const int*)d_in[8];
    // d_in[9] = attention_mask (causal tril) — enforced analytically in flash kernel
    float* out = (float*)d_out;

    float *c1, *q, *kv;
    bf16 *hidh, *hidl, *w1h, *w1l, *qbwh, *qbwl, *kvbwh, *kvbwl;
    bf16 *owh, *owl, *qch, *qcl, *cnh, *cnl, *ath, *atl;
    bf16 *Qhh, *Qhl, *Khh, *Khl, *Vhh, *Vhl;
    cudaGetSymbolAddress((void**)&c1,  g_c1);   cudaGetSymbolAddress((void**)&q,    g_q);
    cudaGetSymbolAddress((void**)&kv,  g_kv);
    cudaGetSymbolAddress((void**)&hidh, g_hidh); cudaGetSymbolAddress((void**)&hidl, g_hidl);
    cudaGetSymbolAddress((void**)&w1h, g_w1h);   cudaGetSymbolAddress((void**)&w1l, g_w1l);
    cudaGetSymbolAddress((void**)&qbwh, g_qbwh); cudaGetSymbolAddress((void**)&qbwl, g_qbwl);
    cudaGetSymbolAddress((void**)&kvbwh, g_kvbwh); cudaGetSymbolAddress((void**)&kvbwl, g_kvbwl);
    cudaGetSymbolAddress((void**)&owh, g_owh);   cudaGetSymbolAddress((void**)&owl, g_owl);
    cudaGetSymbolAddress((void**)&qch, g_qch);   cudaGetSymbolAddress((void**)&qcl, g_qcl);
    cudaGetSymbolAddress((void**)&cnh, g_cnh);   cudaGetSymbolAddress((void**)&cnl, g_cnl);
    cudaGetSymbolAddress((void**)&ath, g_ath);   cudaGetSymbolAddress((void**)&atl, g_atl);
    cudaGetSymbolAddress((void**)&Qhh, g_Qhh);   cudaGetSymbolAddress((void**)&Qhl, g_Qhl);
    cudaGetSymbolAddress((void**)&Khh, g_Khh);   cudaGetSymbolAddress((void**)&Khl, g_Khl);
    cudaGetSymbolAddress((void**)&Vhh, g_Vhh);   cudaGetSymbolAddress((void**)&Vhl, g_Vhl);

    cudaFuncSetAttribute(gemm_tc,    cudaFuncAttributeMaxDynamicSharedMemorySize, GEMM_SMEM);
    cudaFuncSetAttribute(flashmma_k, cudaFuncAttributeMaxDynamicSharedMemorySize, FL_SMEM);

    #define CVT4(x, h, l, n) cvt_pair4_k<<<(unsigned)((((size_t)(n) / 4) + 255) / 256), 256>>>(x, h, l, (size_t)(n) / 4)
    CVT4(hidden, hidh, hidl, (size_t)MTOK * HID);
    CVT4(qaw,    w1h,  w1l,  (size_t)QRANK * HID);            // rows [0, 1536)
    cvt_pad4_k<<<(unsigned)((((size_t)KVAPAD * HID / 4) + 255) / 256), 256>>>(
        kvaw, w1h + (size_t)QRANK * HID, w1l + (size_t)QRANK * HID,
        KVAOUT, HID, KVAPAD);                                 // rows [1536, 2176)
    CVT4(qbw,    qbwh, qbwl, (size_t)QBOUT * QRANK);
    CVT4(kvbw,   kvbwh, kvbwl, (size_t)KVBOUT * KVRANK);
    CVT4(ow,     owh,  owl,  (size_t)HID * ODIM);

    // 1) combined [q_c | ckv] = hidden @ [q_a ; kv_a]^T   [4096, 2176]
    gemm_tc<<<dim3(W1R/TN, MTOK/TM), 256, GEMM_SMEM>>>(hidh, hidl, w1h, w1l, c1, HID, W1R);
    // 2) rmsnorm(q_c) and rmsnorm(ckv[:, :512])
    rmsnorm_pair_k<<<MTOK, 256>>>(c1, qaln, qch, qcl, QRANK, W1R);
    rmsnorm_pair_k<<<MTOK, 256>>>(c1 + QRANK, kvaln, cnh, cnl, KVRANK, W1R);
    // 3) q = qcn @ q_b^T
    gemm_tc<<<dim3(QBOUT/TN, MTOK/TM), 256, GEMM_SMEM>>>(qch, qcl, qbwh, qbwl, q, QRANK, QBOUT);
    // 4) kv = cn @ kv_b^T
    gemm_tc<<<dim3(KVBOUT/TN, MTOK/TM), 256, GEMM_SMEM>>>(cnh, cnl, kvbwh, kvbwl, kv, KVRANK, KVBOUT);
    // 5) build bf16 split Q (rope+scale) and K,V
    build_q_k<<<dim3(SS, NH, BB), 128>>>(q, pos, Qhh, Qhl, rsqrtf((float)DQ));
    build_kv_k<<<dim3(SS, BB), 256>>>(c1 + QRANK, kv, pos, Khh, Khl, Vhh, Vhl);
    // 6) HMMA flash attention -> attn (hi,lo) bf16
    flashmma_k<<<dim3(SS/FQM, BB*NH), 256, FL_SMEM>>>(Qhh, Qhl, Khh, Khl, Vhh, Vhl, ath, atl);
    // 7) out = attn @ o^T
    gemm_tc<<<dim3(HID/TN, MTOK/TM), 256, GEMM_SMEM>>>(ath, atl, owh, owl, out, ODIM, HID);
}

// round 16
// speedup vs baseline: 1.5543x; 1.0026x over previous
#include <cuda_runtime.h>
#include <cuda_bf16.h>
#include <math.h>
#include <stdint.h>

// ---------------- problem constants ----------------
#define BB 2
#define SS 2048
#define HID 5120
#define NH 32
#define DNOPE 128
#define DROPE 64
#define DV 128
#define DQ 192
#define QRANK 1536
#define KVRANK 512
#define MTOK (BB*SS)            // 4096
#define KVAOUT (KVRANK+DROPE)   // 576
#define KVAPAD 640              // kv_a rows padded to /128
#define W1R (QRANK+KVAPAD)      // 2176 combined q_a+kv_a output dim
#define QBOUT (NH*DQ)           // 6144
#define KVBOUT (NH*(DNOPE+DV))  // 8192
#define ODIM  (NH*DV)           // 4096

typedef __nv_bfloat16 bf16;

// ---------------- scratch (static device, allocation-free) ----------------
__device__ float g_c1  [(size_t)MTOK*W1R];     // [q_c | ckv] combined
__device__ float g_q   [(size_t)MTOK*QBOUT];
__device__ float g_kv  [(size_t)MTOK*KVBOUT];
// bf16 hi/lo operand buffers (projections)
__device__ bf16 g_hidh[(size_t)MTOK*HID],   g_hidl[(size_t)MTOK*HID];
__device__ bf16 g_w1h [(size_t)W1R*HID],    g_w1l [(size_t)W1R*HID];   // [qaw ; kvaw(pad)]
__device__ bf16 g_qbwh[(size_t)QBOUT*QRANK],g_qbwl[(size_t)QBOUT*QRANK];
__device__ bf16 g_kvbwh[(size_t)KVBOUT*KVRANK], g_kvbwl[(size_t)KVBOUT*KVRANK];
__device__ bf16 g_owh [(size_t)HID*ODIM],   g_owl [(size_t)HID*ODIM];
__device__ bf16 g_qch [(size_t)MTOK*QRANK], g_qcl [(size_t)MTOK*QRANK];
__device__ bf16 g_cnh [(size_t)MTOK*KVRANK],g_cnl [(size_t)MTOK*KVRANK];
__device__ bf16 g_ath [(size_t)MTOK*ODIM],  g_atl [(size_t)MTOK*ODIM];
// bf16 hi/lo attention operands [b,h][s][*]
__device__ bf16 g_Qhh[(size_t)BB*NH*SS*DQ], g_Qhl[(size_t)BB*NH*SS*DQ];
__device__ bf16 g_Khh[(size_t)BB*NH*SS*DQ], g_Khl[(size_t)BB*NH*SS*DQ];
__device__ bf16 g_Vhh[(size_t)BB*NH*SS*DV], g_Vhl[(size_t)BB*NH*SS*DV];

// ---------------- warp-MMA helpers (plain sm_103-legal PTX) ----------------
__device__ __forceinline__ uint32_t s2u(const void* p) {
    uint32_t a;
    asm("{ .reg .u64 t; cvta.to.shared.u64 t, %1; cvt.u32.u64 %0, t; }" : "=r"(a) : "l"(p));
    return a;
}
#define SWZ128(off) ((off) ^ (((off) >> 3) & 0x70))   // 128B-row panels
#define SWZV(off)   ((off) ^ (((off) >> 4) & 0x70))   // 256B-row V panel

__device__ __forceinline__ void ldmx4(uint32_t r[4], uint32_t a) {
    asm volatile("ldmatrix.sync.aligned.m8n8.x4.shared.b16 {%0,%1,%2,%3}, [%4];"
        : "=r"(r[0]), "=r"(r[1]), "=r"(r[2]), "=r"(r[3]) : "r"(a));
}
__device__ __forceinline__ void ldmx2(uint32_t r[2], uint32_t a) {
    asm volatile("ldmatrix.sync.aligned.m8n8.x2.shared.b16 {%0,%1}, [%2];"
        : "=r"(r[0]), "=r"(r[1]) : "r"(a));
}
__device__ __forceinline__ void ldmx2t(uint32_t r[2], uint32_t a) {
    asm volatile("ldmatrix.sync.aligned.m8n8.x2.trans.shared.b16 {%0,%1}, [%2];"
        : "=r"(r[0]), "=r"(r[1]) : "r"(a));
}
__device__ __forceinline__ void mma16816(float c[4], const uint32_t a[4], const uint32_t b[2]) {
    asm volatile(
        "mma.sync.aligned.m16n8k16.row.col.f32.bf16.bf16.f32 "
        "{%0,%1,%2,%3}, {%4,%5,%6,%7}, {%8,%9}, {%0,%1,%2,%3};"
        : "+f"(c[0]), "+f"(c[1]), "+f"(c[2]), "+f"(c[3])
        : "r"(a[0]), "r"(a[1]), "r"(a[2]), "r"(a[3]), "r"(b[0]), "r"(b[1]));
}
__device__ __forceinline__ uint32_t packbf2(float lo, float hi) {
    __nv_bfloat162 t = __floats2bfloat162_rn(lo, hi);
    return *reinterpret_cast<uint32_t*>(&t);
}
__device__ __forceinline__ void cpa16(uint32_t dst, const void* src) {
    asm volatile("cp.async.cg.shared.global [%0], [%1], 16;" :: "r"(dst), "l"(src));
}
#define CPA_COMMIT() asm volatile("cp.async.commit_group;" ::: "memory")
#define CPA_WAIT1()  asm volatile("cp.async.wait_group 1;" ::: "memory")
#define CPA_WAIT0()  asm volatile("cp.async.wait_group 0;" ::: "memory")

// ===== split-bf16 HMMA GEMM, 128x128 tile, 2-stage cp.async, 1 barrier/chunk =====
#define TM 128
#define TN 128
#define TKC 64
#define SM_AH 0
#define SM_AL 16384
#define SM_BH 32768
#define SM_BL 49152
#define STG_B 65536
#define GEMM_SMEM (2 * STG_B)   // 131072

__global__ __launch_bounds__(256, 1)
void gemm_tc(const bf16* __restrict__ Ah, const bf16* __restrict__ Al,
             const bf16* __restrict__ Bh, const bf16* __restrict__ Bl,
             float* __restrict__ C, int K, int ldc)
{
    extern __shared__ char smem[];
    const uint32_t sb = s2u(smem);
    const int tid = threadIdx.x, wid = tid >> 5, lid = tid & 31;
    const int m0 = blockIdx.y * TM, n0 = blockIdx.x * TN;
    const int wm = wid & 1, wn = wid >> 1;

    const int grow = tid >> 1;
    const int half = tid & 1;
    const uint4* rAh = reinterpret_cast<const uint4*>(Ah + (size_t)(m0 + grow) * K);
    const uint4* rAl = reinterpret_cast<const uint4*>(Al + (size_t)(m0 + grow) * K);
    const uint4* rBh = reinterpret_cast<const uint4*>(Bh + (size_t)(n0 + grow) * K);
    const uint4* rBl = reinterpret_cast<const uint4*>(Bl + (size_t)(n0 + grow) * K);

    uint32_t soff[4];
    #pragma unroll
    for (int j = 0; j < 4; j++)
        soff[j] = SWZ128((uint32_t)(grow * 128 + half * 64 + j * 16));

    float c[4][4][4];
    #pragma unroll
    for (int mt = 0; mt < 4; mt++)
        #pragma unroll
        for (int nt = 0; nt < 4; nt++)
            #pragma unroll
            for (int e = 0; e < 4; e++) c[mt][nt][e] = 0.f;

    const int arow = wm * 64 + (lid & 15);
    const int aq   = lid >> 4;
    const int brow = wn * 32 + (lid & 7);
    const int bq   = (lid >> 3) & 1;

    // prologue: chunk 0 -> stage 0
    {
        const int base = half * 4;
        #pragma unroll
        for (int j = 0; j < 4; j++) {
            cpa16(sb + SM_AH + soff[j], rAh + base + j);
            cpa16(sb + SM_AL + soff[j], rAl + base + j);
            cpa16(sb + SM_BH + soff[j], rBh + base + j);
            cpa16(sb + SM_BL + soff[j], rBl + base + j);
        }
        CPA_COMMIT();
    }

    const int nch = K / TKC;
    for (int ch = 0; ch < nch; ch++) {
        const uint32_t scur = sb + (uint32_t)(ch & 1) * STG_B;
        CPA_WAIT0();
        __syncthreads();
        if (ch + 1 < nch) {
            const uint32_t snxt = sb + (uint32_t)((ch + 1) & 1) * STG_B;
            const int base = (ch + 1) * (TKC / 8) + half * 4;
            #pragma unroll
            for (int j = 0; j < 4; j++) {
                cpa16(snxt + SM_AH + soff[j], rAh + base + j);
                cpa16(snxt + SM_AL + soff[j], rAl + base + j);
                cpa16(snxt + SM_BH + soff[j], rBh + base + j);
                cpa16(snxt + SM_BL + soff[j], rBl + base + j);
            }
            CPA_COMMIT();
        }

        #pragma unroll
        for (int ks = 0; ks < 4; ks++) {
            uint32_t ah[4][4], al[4][4], bh[4][2], bl[4][2];
            #pragma unroll
            for (int mt = 0; mt < 4; mt++) {
                const uint32_t off = SWZ128((uint32_t)((arow + mt * 16) * 128 + (ks * 2 + aq) * 16));
                ldmx4(ah[mt], scur + SM_AH + off);
                ldmx4(al[mt], scur + SM_AL + off);
            }
            #pragma unroll
            for (int nt = 0; nt < 4; nt++) {
                const uint32_t off = SWZ128((uint32_t)((brow + nt * 8) * 128 + (ks * 2 + bq) * 16));
                ldmx2(bh[nt], scur + SM_BH + off);
                ldmx2(bl[nt], scur + SM_BL + off);
            }
            #pragma unroll
            for (int mt = 0; mt < 4; mt++)
                #pragma unroll
                for (int nt = 0; nt < 4; nt++) {
                    mma16816(c[mt][nt], ah[mt], bh[nt]);
                    mma16816(c[mt][nt], ah[mt], bl[nt]);
                    mma16816(c[mt][nt], al[mt], bh[nt]);
                }
        }
    }

    const int mbase = m0 + wm * 64 + (lid >> 2);
    const int nbase = n0 + wn * 32 + (lid & 3) * 2;
    #pragma unroll
    for (int mt = 0; mt < 4; mt++)
        #pragma unroll
        for (int nt = 0; nt < 4; nt++) {
            float* p0 = C + (size_t)(mbase + mt * 16) * ldc + nbase + nt * 8;
            float* p1 = p0 + 8 * ldc;
            *reinterpret_cast<float2*>(p0) = make_float2(c[mt][nt][0], c[mt][nt][1]);
            *reinterpret_cast<float2*>(p1) = make_float2(c[mt][nt][2], c[mt][nt][3]);
        }
}

// ------- fp32 -> (hi,lo) bf16, vectorized 4 elems/thread -------
__global__ __launch_bounds__(256)
void cvt_pair4_k(const float* __restrict__ x, bf16* __restrict__ h,
                 bf16* __restrict__ l, size_t n4)
{
    const size_t i = (size_t)blockIdx.x * 256 + threadIdx.x;
    if (i >= n4) return;
    const float4 v = reinterpret_cast<const float4*>(x)[i];
    const float h0 = __bfloat162float(__float2bfloat16(v.x));
    const float h1 = __bfloat162float(__float2bfloat16(v.y));
    const float h2 = __bfloat162float(__float2bfloat16(v.z));
    const float h3 = __bfloat162float(__float2bfloat16(v.w));
    uint2 hp, lp;
    hp.x = packbf2(h0, h1);          hp.y = packbf2(h2, h3);
    lp.x = packbf2(v.x - h0, v.y - h1); lp.y = packbf2(v.z - h2, v.w - h3);
    reinterpret_cast<uint2*>(h)[i] = hp;
    reinterpret_cast<uint2*>(l)[i] = lp;
}

// pad rows [rows, padrows) with zeros; cols % 4 == 0 so groups never straddle rows
__global__ __launch_bounds__(256)
void cvt_pad4_k(const float* __restrict__ x, bf16* __restrict__ h,
                bf16* __restrict__ l, int rows, int cols, int padrows)
{
    const size_t i = (size_t)blockIdx.x * 256 + threadIdx.x;
    if (i >= (size_t)padrows * (cols / 4)) return;
    const int r = (int)(i / (cols / 4));
    uint2 hp, lp;
    if (r < rows) {
        const float4 v = reinterpret_cast<const float4*>(x)[i];
        const float h0 = __bfloat162float(__float2bfloat16(v.x));
        const float h1 = __bfloat162float(__float2bfloat16(v.y));
        const float h2 = __bfloat162float(__float2bfloat16(v.z));
        const float h3 = __bfloat162float(__float2bfloat16(v.w));
        hp.x = packbf2(h0, h1);          hp.y = packbf2(h2, h3);
        lp.x = packbf2(v.x - h0, v.y - h1); lp.y = packbf2(v.z - h2, v.w - h3);
    } else {
        hp.x = hp.y = lp.x = lp.y = 0u;
    }
    reinterpret_cast<uint2*>(h)[i] = hp;
    reinterpret_cast<uint2*>(l)[i] = lp;
}

// ---------------- RMSNorm -> (hi,lo) bf16 ----------------
__global__ __launch_bounds__(256)
void rmsnorm_pair_k(const float* __restrict__ x, const float* __restrict__ w,
                    bf16* __restrict__ yh, bf16* __restrict__ yl,
                    int n, int in_stride)
{
    const int row = blockIdx.x;
    const float* xr = x + (size_t)row * in_stride;
    bf16* yhr = yh + (size_t)row * n;
    bf16* ylr = yl + (size_t)row * n;
    __shared__ float red[256];
    float s = 0.f;
    for (int i = threadIdx.x; i < n; i += 256) { float v = xr[i]; s += v * v; }
    red[threadIdx.x] = s; __syncthreads();
    for (int o = 128; o; o >>= 1) {
        if (threadIdx.x < o) red[threadIdx.x] += red[threadIdx.x + o];
        __syncthreads();
    }
    const float r = rsqrtf(red[0] / n + 1e-6f);
    for (int i = threadIdx.x; i < n; i += 256) {
        const float v = xr[i] * r * w[i];
        const bf16 hh = __float2bfloat16(v);
        yhr[i] = hh;
        ylr[i] = __float2bfloat16(v - __bfloat162float(hh));
    }
}

// ------- build Q (RoPE + scale) -> bf16 hi/lo [b,h,s,192] -------
__global__ __launch_bounds__(128)
void build_q_k(const float* __restrict__ q, const int* __restrict__ pos,
               bf16* __restrict__ Qhh, bf16* __restrict__ Qhl, float scale)
{
    const int s = blockIdx.x, h = blockIdx.y, b = blockIdx.z;
    const float* in = q + ((size_t)(b * SS + s)) * QBOUT + h * DQ;
    const size_t ob = (((size_t)(b * NH + h) * SS) + s) * DQ;
    const int t = threadIdx.x;
    {
        const float v = in[t] * scale;
        const bf16 hh = __float2bfloat16(v);
        Qhh[ob + t] = hh;
        Qhl[ob + t] = __float2bfloat16(v - __bfloat162float(hh));
    }
    if (t < 32) {
        const float tp = (float)pos[b * SS + s];
        const float f = exp2f((float)t * (-13.2877123795494f / 32.f));
        float c, sn; sincosf(tp * f, &sn, &c);
        const float x0 = in[DNOPE + 2 * t];
        const float x1 = in[DNOPE + 2 * t + 1];
        const float v0 = (x0 * c - x1 * sn) * scale;
        const float v1 = (x1 * c + x0 * sn) * scale;
        bf16 h0 = __float2bfloat16(v0), h1 = __float2bfloat16(v1);
        Qhh[ob + DNOPE + t]      = h0;
        Qhl[ob + DNOPE + t]      = __float2bfloat16(v0 - __bfloat162float(h0));
        Qhh[ob + DNOPE + 32 + t] = h1;
        Qhl[ob + DNOPE + 32 + t] = __float2bfloat16(v1 - __bfloat162float(h1));
    }
}

// ------- build K,V -> bf16 hi/lo [b,h,s,*] (ckv = g_c1 + QRANK, stride W1R) -------
__global__ __launch_bounds__(256)
void build_kv_k(const float* __restrict__ ckv, const float* __restrict__ kv,
                const int* __restrict__ pos,
                bf16* __restrict__ Khh, bf16* __restrict__ Khl,
                bf16* __restrict__ Vhh, bf16* __restrict__ Vhl)
{
    const int s = blockIdx.x, b = blockIdx.y;
    const size_t bs = (size_t)b * SS + s;
    __shared__ float kr[DROPE];
    const int tid = threadIdx.x;
    if (tid < 32) {
        const float tp = (float)pos[bs];
        const float f = exp2f((float)tid * (-13.2877123795494f / 32.f));
        float c, sn; sincosf(tp * f, &sn, &c);
        const float x0 = ckv[bs * W1R + KVRANK + 2 * tid];
        const float x1 = ckv[bs * W1R + KVRANK + 2 * tid + 1];
        kr[tid]      = x0 * c - x1 * sn;
        kr[32 + tid] = x1 * c + x0 * sn;
    }
    __syncthreads();
    const float* kvrow = kv + bs * KVBOUT;
    for (int idx = tid; idx < NH * DQ; idx += 256) {
        const int h = idx / DQ, d = idx % DQ;
        const float v = (d < DNOPE) ? kvrow[h * (DNOPE + DV) + d] : kr[d - DNOPE];
        const size_t o = (((size_t)(b * NH + h) * SS) + s) * DQ + d;
        const bf16 hh = __float2bfloat16(v);
        Khh[o] = hh;
        Khl[o] = __float2bfloat16(v - __bfloat162float(hh));
    }
    for (int idx = tid; idx < NH * DV; idx += 256) {
        const int h = idx / DV, d = idx % DV;
        const float v = kvrow[h * (DNOPE + DV) + DNOPE + d];
        const size_t o = (((size_t)(b * NH + h) * SS) + s) * DV + d;
        const bf16 hh = __float2bfloat16(v);
        Vhh[o] = hh;
        Vhl[o] = __float2bfloat16(v - __bfloat162float(hh));
    }
}

// ====== HMMA flash attention, cp.async pipelined K (2-stage) + early V ======
// longest-first CTA order: qt = gridDim.x-1-blockIdx.x (heaviest tiles start in wave 0)
#define FQM 128
#define FKN 64
#define FQH0 0
#define FQL0 49152
#define FKS0 98304
#define FKSTG 49152
#define FVH0 196608
#define FVL0 212992
#define FL_SMEM 229376

__global__ __launch_bounds__(256, 1)
void flashmma_k(const bf16* __restrict__ Qhh, const bf16* __restrict__ Qhl,
                const bf16* __restrict__ Khh, const bf16* __restrict__ Khl,
                const bf16* __restrict__ Vhh, const bf16* __restrict__ Vhl,
                bf16* __restrict__ ath, bf16* __restrict__ atl)
{
    extern __shared__ char sm[];
    const uint32_t sb = s2u(sm);
    const int tid = threadIdx.x, w = tid >> 5, l = tid & 31;
    const int qt = (int)gridDim.x - 1 - (int)blockIdx.x;   // heavy CTAs first
    const int bh = blockIdx.y;
    const int b = bh / NH, h = bh % NH;
    const int q0 = qt * FQM;

    {
        const uint4* Kh4 = reinterpret_cast<const uint4*>(Khh + (size_t)bh * SS * DQ);
        const uint4* Kl4 = reinterpret_cast<const uint4*>(Khl + (size_t)bh * SS * DQ);
        for (int idx = tid; idx < 64 * 24; idx += 256) {
            const int row = idx / 24, u = idx % 24;
            const int p = u >> 3, qd = u & 7;
            const uint32_t off = (uint32_t)(p * 8192) + SWZ128((uint32_t)(row * 128 + qd * 16));
            cpa16(sb + FKS0 + off,         Kh4 + row * 24 + u);
            cpa16(sb + FKS0 + 24576 + off, Kl4 + row * 24 + u);
        }
        CPA_COMMIT();
    }

    {
        const uint4* Qh4 = reinterpret_cast<const uint4*>(Qhh + ((size_t)bh * SS + q0) * DQ);
        const uint4* Ql4 = reinterpret_cast<const uint4*>(Qhl + ((size_t)bh * SS + q0) * DQ);
        for (int idx = tid; idx < 128 * 24; idx += 256) {
            const int row = idx / 24, u = idx % 24;
            const int p = u >> 3, qd = u & 7;
            const uint32_t off = (uint32_t)(p * 16384) + SWZ128((uint32_t)(row * 128 + qd * 16));
            *reinterpret_cast<uint4*>(sm + FQH0 + off) = Qh4[row * 24 + u];
            *reinterpret_cast<uint4*>(sm + FQL0 + off) = Ql4[row * 24 + u];
        }
    }

    float oacc[16][4];
    #pragma unroll
    for (int i = 0; i < 16; i++)
        #pragma unroll
        for (int e = 0; e < 4; e++) oacc[i][e] = 0.f;
    float mrow[2] = {-1e30f, -1e30f};
    float lsum[2] = {0.f, 0.f};

    const int r0 = q0 + w * 16 + (l >> 2);
    const int r1 = r0 + 8;

    const int ktmax = 2 * qt + 1;
    for (int kt = 0; kt <= ktmax; kt++) {
        const int k0 = kt * FKN;
        const uint32_t kcur = sb + FKS0 + (uint32_t)(kt & 1) * FKSTG;

        {
            const uint4* Vh4 = reinterpret_cast<const uint4*>(Vhh + ((size_t)bh * SS + k0) * DV);
            const uint4* Vl4 = reinterpret_cast<const uint4*>(Vhl + ((size_t)bh * SS + k0) * DV);
            for (int idx = tid; idx < 64 * 16; idx += 256) {
                const int row = idx >> 4, qd = idx & 15;
                const uint32_t off = SWZV((uint32_t)(row * 256 + qd * 16));
                cpa16(sb + FVH0 + off, Vh4 + row * 16 + qd);
                cpa16(sb + FVL0 + off, Vl4 + row * 16 + qd);
            }
            if (kt < ktmax) {
                const uint32_t knxt = sb + FKS0 + (uint32_t)((kt + 1) & 1) * FKSTG;
                const uint4* Kh4 = reinterpret_cast<const uint4*>(Khh + ((size_t)bh * SS + k0 + FKN) * DQ);
                const uint4* Kl4 = reinterpret_cast<const uint4*>(Khl + ((size_t)bh * SS + k0 + FKN) * DQ);
                for (int idx = tid; idx < 64 * 24; idx += 256) {
                    const int row = idx / 24, u = idx % 24;
                    const int p = u >> 3, qd = u & 7;
                    const uint32_t off = (uint32_t)(p * 8192) + SWZ128((uint32_t)(row * 128 + qd * 16));
                    cpa16(knxt + off,         Kh4 + row * 24 + u);
                    cpa16(knxt + 24576 + off, Kl4 + row * 24 + u);
                }
            }
            CPA_COMMIT();
        }
        CPA_WAIT1();
        __syncthreads();

        float sacc[8][4];
        #pragma unroll
        for (int nt = 0; nt < 8; nt++)
            #pragma unroll
            for (int e = 0; e < 4; e++) sacc[nt][e] = 0.f;

        #pragma unroll
        for (int p = 0; p < 3; p++)
            #pragma unroll
            for (int ks = 0; ks < 4; ks++) {
                uint32_t ah[4], al[4];
                const uint32_t aoff = (uint32_t)(p * 16384) +
                    SWZ128((uint32_t)((w * 16 + (l & 15)) * 128 + (ks * 2 + (l >> 4)) * 16));
                ldmx4(ah, sb + FQH0 + aoff);
                ldmx4(al, sb + FQL0 + aoff);
                #pragma unroll
                for (int nt = 0; nt < 8; nt++) {
                    uint32_t bh_[2], bl_[2];
                    const uint32_t boff = (uint32_t)(p * 8192) +
                        SWZ128((uint32_t)((nt * 8 + (l & 7)) * 128 + (ks * 2 + ((l >> 3) & 1)) * 16));
                    ldmx2(bh_, kcur + boff);
                    ldmx2(bl_, kcur + 24576 + boff);
                    mma16816(sacc[nt], ah, bh_);
                    mma16816(sacc[nt], ah, bl_);
                    mma16816(sacc[nt], al, bh_);
                }
            }

        if (kt >= 2 * qt) {
            #pragma unroll
            for (int nt = 0; nt < 8; nt++) {
                const int c0 = k0 + nt * 8 + (l & 3) * 2;
                if (c0     > r0) sacc[nt][0] = -1e30f;
                if (c0 + 1 > r0) sacc[nt][1] = -1e30f;
                if (c0     > r1) sacc[nt][2] = -1e30f;
                if (c0 + 1 > r1) sacc[nt][3] = -1e30f;
            }
        }

        float alpha[2];
        #pragma unroll
        for (int sub = 0; sub < 2; sub++) {
            float tm = -1e30f;
            #pragma unroll
            for (int nt = 0; nt < 8; nt++)
                tm = fmaxf(tm, fmaxf(sacc[nt][2 * sub], sacc[nt][2 * sub + 1]));
            tm = fmaxf(tm, __shfl_xor_sync(0xffffffffu, tm, 1));
            tm = fmaxf(tm, __shfl_xor_sync(0xffffffffu, tm, 2));
            const float mn = fmaxf(mrow[sub], tm);
            alpha[sub] = __expf(mrow[sub] - mn);
            float rs = 0.f;
            #pragma unroll
            for (int nt = 0; nt < 8; nt++) {
                sacc[nt][2 * sub]     = __expf(sacc[nt][2 * sub] - mn);
                sacc[nt][2 * sub + 1] = __expf(sacc[nt][2 * sub + 1] - mn);
                rs += sacc[nt][2 * sub] + sacc[nt][2 * sub + 1];
            }
            rs += __shfl_xor_sync(0xffffffffu, rs, 1);
            rs += __shfl_xor_sync(0xffffffffu, rs, 2);
            lsum[sub] = lsum[sub] * alpha[sub] + rs;
            mrow[sub] = mn;
        }
        #pragma unroll
        for (int ntv = 0; ntv < 16; ntv++) {
            oacc[ntv][0] *= alpha[0]; oacc[ntv][1] *= alpha[0];
            oacc[ntv][2] *= alpha[1]; oacc[ntv][3] *= alpha[1];
        }

        CPA_WAIT0();
        __syncthreads();

        #pragma unroll
        for (int kt4 = 0; kt4 < 4; kt4++) {
            uint32_t pah[4], pal[4];
            {
                const float* s0 = sacc[2 * kt4];
                const float* s1 = sacc[2 * kt4 + 1];
                float h00 = __bfloat162float(__float2bfloat16(s0[0]));
                float h01 = __bfloat162float(__float2bfloat16(s0[1]));
                float h02 = __bfloat162float(__float2bfloat16(s0[2]));
                float h03 = __bfloat162float(__float2bfloat16(s0[3]));
                float h10 = __bfloat162float(__float2bfloat16(s1[0]));
                float h11 = __bfloat162float(__float2bfloat16(s1[1]));
                float h12 = __bfloat162float(__float2bfloat16(s1[2]));
                float h13 = __bfloat162float(__float2bfloat16(s1[3]));
                pah[0] = packbf2(h00, h01); pah[1] = packbf2(h02, h03);
                pah[2] = packbf2(h10, h11); pah[3] = packbf2(h12, h13);
                pal[0] = packbf2(s0[0] - h00, s0[1] - h01);
                pal[1] = packbf2(s0[2] - h02, s0[3] - h03);
                pal[2] = packbf2(s1[0] - h10, s1[1] - h11);
                pal[3] = packbf2(s1[2] - h12, s1[3] - h13);
            }
            #pragma unroll
            for (int ntv = 0; ntv < 16; ntv++) {
                uint32_t bvh[2], bvl[2];
                const uint32_t voff =
                    SWZV((uint32_t)((kt4 * 16 + (l & 7) + ((l >> 3) & 1) * 8) * 256 + ntv * 16));
                ldmx2t(bvh, sb + FVH0 + voff);
                ldmx2t(bvl, sb + FVL0 + voff);
                mma16816(oacc[ntv], pah, bvh);
                mma16816(oacc[ntv], pah, bvl);
                mma16816(oacc[ntv], pal, bvh);
            }
        }
        __syncthreads();
    }

    const float inv0 = 1.f / lsum[0];
    const float inv1 = 1.f / lsum[1];
    const size_t row0 = (size_t)(b * SS + r0) * ODIM + h * DV;
    const size_t row1 = (size_t)(b * SS + r1) * ODIM + h * DV;
    #pragma unroll
    for (int ntv = 0; ntv < 16; ntv++) {
        const int col = ntv * 8 + (l & 3) * 2;
        const float v00 = oacc[ntv][0] * inv0, v01 = oacc[ntv][1] * inv0;
        const float v10 = oacc[ntv][2] * inv1, v11 = oacc[ntv][3] * inv1;
        float h00 = __bfloat162float(__float2bfloat16(v00));
        float h01 = __bfloat162float(__float2bfloat16(v01));
        float h10 = __bfloat162float(__float2bfloat16(v10));
        float h11 = __bfloat162float(__float2bfloat16(v11));
        *reinterpret_cast<uint32_t*>(&ath[row0 + col]) = packbf2(h00, h01);
        *reinterpret_cast<uint32_t*>(&atl[row0 + col]) = packbf2(v00 - h00, v01 - h01);
        *reinterpret_cast<uint32_t*>(&ath[row1 + col]) = packbf2(h10, h11);
        *reinterpret_cast<uint32_t*>(&atl[row1 + col]) = packbf2(v10 - h10, v11 - h11);
    }
}

// ---------------- launch ----------------
extern "C" void kernel_launch(void* const* d_in, const int* in_sizes, int n_in,
                              void* d_out, int out_size)
{
    const float* hidden = (const float*)d_in[0];
    const float* qaw    = (const float*)d_in[1];
    const float* qaln   = (const float*)d_in[2];
    const float* qbw    = (const float*)d_in[3];
    const float* kvaw   = (const float*)d_in[4];
    const float* kvaln  = (const float*)d_in[5];
    const float* kvbw   = (const float*)d_in[6];
    const float* ow     = (const float*)d_in[7];
    const int*   pos    = (const int*)d_in[8];
    // d_in[9] = attention_mask (causal tril) — enforced analytically in flash kernel
    float* out = (float*)d_out;

    float *c1, *q, *kv;
    bf16 *hidh, *hidl, *w1h, *w1l, *qbwh, *qbwl, *kvbwh, *kvbwl;
    bf16 *owh, *owl, *qch, *qcl, *cnh, *cnl, *ath, *atl;
    bf16 *Qhh, *Qhl, *Khh, *Khl, *Vhh, *Vhl;
    cudaGetSymbolAddress((void**)&c1,  g_c1);   cudaGetSymbolAddress((void**)&q,    g_q);
    cudaGetSymbolAddress((void**)&kv,  g_kv);
    cudaGetSymbolAddress((void**)&hidh, g_hidh); cudaGetSymbolAddress((void**)&hidl, g_hidl);
    cudaGetSymbolAddress((void**)&w1h, g_w1h);   cudaGetSymbolAddress((void**)&w1l, g_w1l);
    cudaGetSymbolAddress((void**)&qbwh, g_qbwh); cudaGetSymbolAddress((void**)&qbwl, g_qbwl);
    cudaGetSymbolAddress((void**)&kvbwh, g_kvbwh); cudaGetSymbolAddress((void**)&kvbwl, g_kvbwl);
    cudaGetSymbolAddress((void**)&owh, g_owh);   cudaGetSymbolAddress((void**)&owl, g_owl);
    cudaGetSymbolAddress((void**)&qch, g_qch);   cudaGetSymbolAddress((void**)&qcl, g_qcl);
    cudaGetSymbolAddress((void**)&cnh, g_cnh);   cudaGetSymbolAddress((void**)&cnl, g_cnl);
    cudaGetSymbolAddress((void**)&ath, g_ath);   cudaGetSymbolAddress((void**)&atl, g_atl);
    cudaGetSymbolAddress((void**)&Qhh, g_Qhh);   cudaGetSymbolAddress((void**)&Qhl, g_Qhl);
    cudaGetSymbolAddress((void**)&Khh, g_Khh);   cudaGetSymbolAddress((void**)&Khl, g_Khl);
    cudaGetSymbolAddress((void**)&Vhh, g_Vhh);   cudaGetSymbolAddress((void**)&Vhl, g_Vhl);

    cudaFuncSetAttribute(gemm_tc,    cudaFuncAttributeMaxDynamicSharedMemorySize, GEMM_SMEM);
    cudaFuncSetAttribute(flashmma_k, cudaFuncAttributeMaxDynamicSharedMemorySize, FL_SMEM);

    #define CVT4(x, h, l, n) cvt_pair4_k<<<(unsigned)((((size_t)(n) / 4) + 255) / 256), 256>>>(x, h, l, (size_t)(n) / 4)
    // launches 1-5 (ncu -s 5 then captures launch #6 = first gemm_tc)
    CVT4(hidden, hidh, hidl, (size_t)MTOK * HID);
    CVT4(qaw,    w1h,  w1l,  (size_t)QRANK * HID);            // rows [0, 1536)
    cvt_pad4_k<<<(unsigned)((((size_t)KVAPAD * HID / 4) + 255) / 256), 256>>>(
        kvaw, w1h + (size_t)QRANK * HID, w1l + (size_t)QRANK * HID,
        KVAOUT, HID, KVAPAD);                                 // rows [1536, 2176)
    CVT4(qbw,    qbwh, qbwl, (size_t)QBOUT * QRANK);
    CVT4(kvbw,   kvbwh, kvbwl, (size_t)KVBOUT * KVRANK);

    // 1) combined [q_c | ckv] = hidden @ [q_a ; kv_a]^T   [4096, 2176]  (launch #6 -> profiled)
    gemm_tc<<<dim3(W1R/TN, MTOK/TM), 256, GEMM_SMEM>>>(hidh, hidl, w1h, w1l, c1, HID, W1R);
    // o_proj weight cvt (only needed before step 7; moved here so ncu catches gemm above)
    CVT4(ow, owh, owl, (size_t)HID * ODIM);
    // 2) rmsnorm(q_c) and rmsnorm(ckv[:, :512])
    rmsnorm_pair_k<<<MTOK, 256>>>(c1, qaln, qch, qcl, QRANK, W1R);
    rmsnorm_pair_k<<<MTOK, 256>>>(c1 + QRANK, kvaln, cnh, cnl, KVRANK, W1R);
    // 3) q = qcn @ q_b^T
    gemm_tc<<<dim3(QBOUT/TN, MTOK/TM), 256, GEMM_SMEM>>>(qch, qcl, qbwh, qbwl, q, QRANK, QBOUT);
    // 4) kv = cn @ kv_b^T
    gemm_tc<<<dim3(KVBOUT/TN, MTOK/TM), 256, GEMM_SMEM>>>(cnh, cnl, kvbwh, kvbwl, kv, KVRANK, KVBOUT);
    // 5) build bf16 split Q (rope+scale) and K,V
    build_q_k<<<dim3(SS, NH, BB), 128>>>(q, pos, Qhh, Qhl, rsqrtf((float)DQ));
    build_kv_k<<<dim3(SS, BB), 256>>>(c1 + QRANK, kv, pos, Khh, Khl, Vhh, Vhl);
    // 6) HMMA flash attention -> attn (hi,lo) bf16
    flashmma_k<<<dim3(SS/FQM, BB*NH), 256, FL_SMEM>>>(Qhh, Qhl, Khh, Khl, Vhh, Vhl, ath, atl);
    // 7) out = attn @ o^T
    gemm_tc<<<dim3(HID/TN, MTOK/TM), 256, GEMM_SMEM>>>(ath, atl, owh, owl, out, ODIM, HID);
}

// round 17
// speedup vs baseline: 1.5941x; 1.0256x over previous
#include <cuda_runtime.h>
#include <cuda_bf16.h>
#include <math.h>
#include <stdint.h>

// ---------------- problem constants ----------------
#define BB 2
#define SS 2048
#define HID 5120
#define NH 32
#define DNOPE 128
#define DROPE 64
#define DV 128
#define DQ 192
#define QRANK 1536
#define KVRANK 512
#define MTOK (BB*SS)            // 4096
#define KVAOUT (KVRANK+DROPE)   // 576
#define KVAPAD 640              // kv_a rows padded to /128
#define W1R (QRANK+KVAPAD)      // 2176 combined q_a+kv_a output dim
#define QBOUT (NH*DQ)           // 6144
#define KVBOUT (NH*(DNOPE+DV))  // 8192
#define ODIM  (NH*DV)           // 4096

typedef __nv_bfloat16 bf16;

// ---------------- scratch (static device, allocation-free) ----------------
__device__ float g_c1   [(size_t)MTOK*W1R];        // [q_c | ckv] combined
__device__ float g_qrope[(size_t)MTOK*NH*DROPE];   // pre-rope q_pe fp32 scratch
// bf16 hi/lo operand buffers (projections)
__device__ bf16 g_hidh[(size_t)MTOK*HID],   g_hidl[(size_t)MTOK*HID];
__device__ bf16 g_w1h [(size_t)W1R*HID],    g_w1l [(size_t)W1R*HID];
__device__ bf16 g_qbwh[(size_t)QBOUT*QRANK],g_qbwl[(size_t)QBOUT*QRANK];
__device__ bf16 g_kvbwh[(size_t)KVBOUT*KVRANK], g_kvbwl[(size_t)KVBOUT*KVRANK];
__device__ bf16 g_owh [(size_t)HID*ODIM],   g_owl [(size_t)HID*ODIM];
__device__ bf16 g_qch [(size_t)MTOK*QRANK], g_qcl [(size_t)MTOK*QRANK];
__device__ bf16 g_cnh [(size_t)MTOK*KVRANK],g_cnl [(size_t)MTOK*KVRANK];
__device__ bf16 g_ath [(size_t)MTOK*ODIM],  g_atl [(size_t)MTOK*ODIM];
// bf16 hi/lo attention operands [b,h][s][*]
__device__ bf16 g_Qhh[(size_t)BB*NH*SS*DQ], g_Qhl[(size_t)BB*NH*SS*DQ];
__device__ bf16 g_Khh[(size_t)BB*NH*SS*DQ], g_Khl[(size_t)BB*NH*SS*DQ];
__device__ bf16 g_Vhh[(size_t)BB*NH*SS*DV], g_Vhl[(size_t)BB*NH*SS*DV];

// ---------------- warp-MMA helpers (plain sm_103-legal PTX) ----------------
__device__ __forceinline__ uint32_t s2u(const void* p) {
    uint32_t a;
    asm("{ .reg .u64 t; cvta.to.shared.u64 t, %1; cvt.u32.u64 %0, t; }" : "=r"(a) : "l"(p));
    return a;
}
#define SWZ128(off) ((off) ^ (((off) >> 3) & 0x70))   // 128B-row panels
#define SWZV(off)   ((off) ^ (((off) >> 4) & 0x70))   // 256B-row V panel

__device__ __forceinline__ void ldmx4(uint32_t r[4], uint32_t a) {
    asm volatile("ldmatrix.sync.aligned.m8n8.x4.shared.b16 {%0,%1,%2,%3}, [%4];"
        : "=r"(r[0]), "=r"(r[1]), "=r"(r[2]), "=r"(r[3]) : "r"(a));
}
__device__ __forceinline__ void ldmx2(uint32_t r[2], uint32_t a) {
    asm volatile("ldmatrix.sync.aligned.m8n8.x2.shared.b16 {%0,%1}, [%2];"
        : "=r"(r[0]), "=r"(r[1]) : "r"(a));
}
__device__ __forceinline__ void ldmx2t(uint32_t r[2], uint32_t a) {
    asm volatile("ldmatrix.sync.aligned.m8n8.x2.trans.shared.b16 {%0,%1}, [%2];"
        : "=r"(r[0]), "=r"(r[1]) : "r"(a));
}
__device__ __forceinline__ void mma16816(float c[4], const uint32_t a[4], const uint32_t b[2]) {
    asm volatile(
        "mma.sync.aligned.m16n8k16.row.col.f32.bf16.bf16.f32 "
        "{%0,%1,%2,%3}, {%4,%5,%6,%7}, {%8,%9}, {%0,%1,%2,%3};"
        : "+f"(c[0]), "+f"(c[1]), "+f"(c[2]), "+f"(c[3])
        : "r"(a[0]), "r"(a[1]), "r"(a[2]), "r"(a[3]), "r"(b[0]), "r"(b[1]));
}
__device__ __forceinline__ uint32_t packbf2(float lo, float hi) {
    __nv_bfloat162 t = __floats2bfloat162_rn(lo, hi);
    return *reinterpret_cast<uint32_t*>(&t);
}
// split-store a pair of fp32 into (hi,lo) bf16 arrays at element offset o (o even)
__device__ __forceinline__ void st_pair(bf16* __restrict__ H, bf16* __restrict__ L,
                                        size_t o, float v0, float v1) {
    const float h0 = __bfloat162float(__float2bfloat16(v0));
    const float h1 = __bfloat162float(__float2bfloat16(v1));
    *reinterpret_cast<uint32_t*>(&H[o]) = packbf2(h0, h1);
    *reinterpret_cast<uint32_t*>(&L[o]) = packbf2(v0 - h0, v1 - h1);
}
__device__ __forceinline__ void cpa16(uint32_t dst, const void* src) {
    asm volatile("cp.async.cg.shared.global [%0], [%1], 16;" :: "r"(dst), "l"(src));
}
#define CPA_COMMIT() asm volatile("cp.async.commit_group;" ::: "memory")
#define CPA_WAIT1()  asm volatile("cp.async.wait_group 1;" ::: "memory")
#define CPA_WAIT0()  asm volatile("cp.async.wait_group 0;" ::: "memory")

// ===== split-bf16 HMMA GEMM, 128x128 tile, 2-stage cp.async =====
// MODE 0: C fp32 (ldc). MODE 1: Q-out (Oh/Ol nope + rsc rope fp32, scale).
// MODE 2: KV-out (Oh/Ol = K nope, O2h/O2l = V).
#define TM 128
#define TN 128
#define TKC 64
#define SM_AH 0
#define SM_AL 16384
#define SM_BH 32768
#define SM_BL 49152
#define STG_B 65536
#define GEMM_SMEM (2 * STG_B)   // 131072

template<int MODE>
__global__ __launch_bounds__(256, 1)
void gemm_tc(const bf16* __restrict__ Ah, const bf16* __restrict__ Al,
             const bf16* __restrict__ Bh, const bf16* __restrict__ Bl,
             float* __restrict__ C, int K, int ldc,
             bf16* __restrict__ Oh, bf16* __restrict__ Ol,
             bf16* __restrict__ O2h, bf16* __restrict__ O2l,
             float* __restrict__ rsc, float scale)
{
    extern __shared__ char smem[];
    const uint32_t sb = s2u(smem);
    const int tid = threadIdx.x, wid = tid >> 5, lid = tid & 31;
    const int m0 = blockIdx.y * TM, n0 = blockIdx.x * TN;
    const int wm = wid & 1, wn = wid >> 1;

    const int grow = tid >> 1;
    const int half = tid & 1;
    const uint4* rAh = reinterpret_cast<const uint4*>(Ah + (size_t)(m0 + grow) * K);
    const uint4* rAl = reinterpret_cast<const uint4*>(Al + (size_t)(m0 + grow) * K);
    const uint4* rBh = reinterpret_cast<const uint4*>(Bh + (size_t)(n0 + grow) * K);
    const uint4* rBl = reinterpret_cast<const uint4*>(Bl + (size_t)(n0 + grow) * K);

    uint32_t soff[4];
    #pragma unroll
    for (int j = 0; j < 4; j++)
        soff[j] = SWZ128((uint32_t)(grow * 128 + half * 64 + j * 16));

    float c[4][4][4];
    #pragma unroll
    for (int mt = 0; mt < 4; mt++)
        #pragma unroll
        for (int nt = 0; nt < 4; nt++)
            #pragma unroll
            for (int e = 0; e < 4; e++) c[mt][nt][e] = 0.f;

    const int arow = wm * 64 + (lid & 15);
    const int aq   = lid >> 4;
    const int brow = wn * 32 + (lid & 7);
    const int bq   = (lid >> 3) & 1;

    {
        const int base = half * 4;
        #pragma unroll
        for (int j = 0; j < 4; j++) {
            cpa16(sb + SM_AH + soff[j], rAh + base + j);
            cpa16(sb + SM_AL + soff[j], rAl + base + j);
            cpa16(sb + SM_BH + soff[j], rBh + base + j);
            cpa16(sb + SM_BL + soff[j], rBl + base + j);
        }
        CPA_COMMIT();
    }

    const int nch = K / TKC;
    for (int ch = 0; ch < nch; ch++) {
        const uint32_t scur = sb + (uint32_t)(ch & 1) * STG_B;
        CPA_WAIT0();
        __syncthreads();
        if (ch + 1 < nch) {
            const uint32_t snxt = sb + (uint32_t)((ch + 1) & 1) * STG_B;
            const int base = (ch + 1) * (TKC / 8) + half * 4;
            #pragma unroll
            for (int j = 0; j < 4; j++) {
                cpa16(snxt + SM_AH + soff[j], rAh + base + j);
                cpa16(snxt + SM_AL + soff[j], rAl + base + j);
                cpa16(snxt + SM_BH + soff[j], rBh + base + j);
                cpa16(snxt + SM_BL + soff[j], rBl + base + j);
            }
            CPA_COMMIT();
        }

        #pragma unroll
        for (int ks = 0; ks < 4; ks++) {
            uint32_t ah[4][4], al[4][4], bh[4][2], bl[4][2];
            #pragma unroll
            for (int mt = 0; mt < 4; mt++) {
                const uint32_t off = SWZ128((uint32_t)((arow + mt * 16) * 128 + (ks * 2 + aq) * 16));
                ldmx4(ah[mt], scur + SM_AH + off);
                ldmx4(al[mt], scur + SM_AL + off);
            }
            #pragma unroll
            for (int nt = 0; nt < 4; nt++) {
                const uint32_t off = SWZ128((uint32_t)((brow + nt * 8) * 128 + (ks * 2 + bq) * 16));
                ldmx2(bh[nt], scur + SM_BH + off);
                ldmx2(bl[nt], scur + SM_BL + off);
            }
            #pragma unroll
            for (int mt = 0; mt < 4; mt++)
                #pragma unroll
                for (int nt = 0; nt < 4; nt++) {
                    mma16816(c[mt][nt], ah[mt], bh[nt]);
                    mma16816(c[mt][nt], ah[mt], bl[nt]);
                    mma16816(c[mt][nt], al[mt], bh[nt]);
                }
        }
    }

    const int mbase = m0 + wm * 64 + (lid >> 2);
    const int nbase = n0 + wn * 32 + (lid & 3) * 2;

    if (MODE == 0) {
        #pragma unroll
        for (int mt = 0; mt < 4; mt++)
            #pragma unroll
            for (int nt = 0; nt < 4; nt++) {
                float* p0 = C + (size_t)(mbase + mt * 16) * ldc + nbase + nt * 8;
                float* p1 = p0 + 8 * ldc;
                *reinterpret_cast<float2*>(p0) = make_float2(c[mt][nt][0], c[mt][nt][1]);
                *reinterpret_cast<float2*>(p1) = make_float2(c[mt][nt][2], c[mt][nt][3]);
            }
    } else {
        #pragma unroll
        for (int mt = 0; mt < 4; mt++) {
            const int m  = mbase + mt * 16;          // rows m, m+8 (same b: tiles 128-aligned)
            const int b0 = m >> 11;                  // SS = 2048
            const int s0 = m & (SS - 1);
            #pragma unroll
            for (int nt = 0; nt < 4; nt++) {
                const int n = nbase + nt * 8;        // cols n, n+1 (n even)
                const float v0 = c[mt][nt][0], v1 = c[mt][nt][1];
                const float v2 = c[mt][nt][2], v3 = c[mt][nt][3];
                if (MODE == 1) {
                    const int h = n / DQ;
                    const int d = n - h * DQ;        // even; pair never straddles 128
                    if (d < DNOPE) {
                        const size_t o0 = (((size_t)(b0 * NH + h)) * SS + s0) * DQ + d;
                        st_pair(Oh, Ol, o0,          v0 * scale, v1 * scale);
                        st_pair(Oh, Ol, o0 + 8 * DQ, v2 * scale, v3 * scale);
                    } else {
                        const size_t r = ((size_t)m * NH + h) * DROPE + (d - DNOPE);
                        *reinterpret_cast<float2*>(&rsc[r])                   = make_float2(v0, v1);
                        *reinterpret_cast<float2*>(&rsc[r + 8 * NH * DROPE])  = make_float2(v2, v3);
                    }
                } else {                             // MODE 2: KV
                    const int h = n >> 8;
                    const int d = n & 255;           // even; pair never straddles 128
                    if (d < DNOPE) {                 // K nope
                        const size_t o0 = (((size_t)(b0 * NH + h)) * SS + s0) * DQ + d;
                        st_pair(Oh, Ol, o0,          v0, v1);
                        st_pair(Oh, Ol, o0 + 8 * DQ, v2, v3);
                    } else {                         // V
                        const size_t o0 = (((size_t)(b0 * NH + h)) * SS + s0) * DV + (d - DNOPE);
                        st_pair(O2h, O2l, o0,          v0, v1);
                        st_pair(O2h, O2l, o0 + 8 * DV, v2, v3);
                    }
                }
            }
        }
    }
}

// ------- fp32 -> (hi,lo) bf16, vectorized 4 elems/thread -------
__global__ __launch_bounds__(256)
void cvt_pair4_k(const float* __restrict__ x, bf16* __restrict__ h,
                 bf16* __restrict__ l, size_t n4)
{
    const size_t i = (size_t)blockIdx.x * 256 + threadIdx.x;
    if (i >= n4) return;
    const float4 v = reinterpret_cast<const float4*>(x)[i];
    const float h0 = __bfloat162float(__float2bfloat16(v.x));
    const float h1 = __bfloat162float(__float2bfloat16(v.y));
    const float h2 = __bfloat162float(__float2bfloat16(v.z));
    const float h3 = __bfloat162float(__float2bfloat16(v.w));
    uint2 hp, lp;
    hp.x = packbf2(h0, h1);          hp.y = packbf2(h2, h3);
    lp.x = packbf2(v.x - h0, v.y - h1); lp.y = packbf2(v.z - h2, v.w - h3);
    reinterpret_cast<uint2*>(h)[i] = hp;
    reinterpret_cast<uint2*>(l)[i] = lp;
}

__global__ __launch_bounds__(256)
void cvt_pad4_k(const float* __restrict__ x, bf16* __restrict__ h,
                bf16* __restrict__ l, int rows, int cols, int padrows)
{
    const size_t i = (size_t)blockIdx.x * 256 + threadIdx.x;
    if (i >= (size_t)padrows * (cols / 4)) return;
    const int r = (int)(i / (cols / 4));
    uint2 hp, lp;
    if (r < rows) {
        const float4 v = reinterpret_cast<const float4*>(x)[i];
        const float h0 = __bfloat162float(__float2bfloat16(v.x));
        const float h1 = __bfloat162float(__float2bfloat16(v.y));
        const float h2 = __bfloat162float(__float2bfloat16(v.z));
        const float h3 = __bfloat162float(__float2bfloat16(v.w));
        hp.x = packbf2(h0, h1);          hp.y = packbf2(h2, h3);
        lp.x = packbf2(v.x - h0, v.y - h1); lp.y = packbf2(v.z - h2, v.w - h3);
    } else {
        hp.x = hp.y = lp.x = lp.y = 0u;
    }
    reinterpret_cast<uint2*>(h)[i] = hp;
    reinterpret_cast<uint2*>(l)[i] = lp;
}

// ---------------- RMSNorm -> (hi,lo) bf16 ----------------
__global__ __launch_bounds__(256)
void rmsnorm_pair_k(const float* __restrict__ x, const float* __restrict__ w,
                    bf16* __restrict__ yh, bf16* __restrict__ yl,
                    int n, int in_stride)
{
    const int row = blockIdx.x;
    const float* xr = x + (size_t)row * in_stride;
    bf16* yhr = yh + (size_t)row * n;
    bf16* ylr = yl + (size_t)row * n;
    __shared__ float red[256];
    float s = 0.f;
    for (int i = threadIdx.x; i < n; i += 256) { float v = xr[i]; s += v * v; }
    red[threadIdx.x] = s; __syncthreads();
    for (int o = 128; o; o >>= 1) {
        if (threadIdx.x < o) red[threadIdx.x] += red[threadIdx.x + o];
        __syncthreads();
    }
    const float r = rsqrtf(red[0] / n + 1e-6f);
    for (int i = threadIdx.x; i < n; i += 256) {
        const float v = xr[i] * r * w[i];
        const bf16 hh = __float2bfloat16(v);
        yhr[i] = hh;
        ylr[i] = __float2bfloat16(v - __bfloat162float(hh));
    }
}

// ------- rope on q_pe scratch -> Qhh/Qhl[128..191] -------
__global__ __launch_bounds__(128)
void build_qrope_k(const float* __restrict__ qr, const int* __restrict__ pos,
                   bf16* __restrict__ Qhh, bf16* __restrict__ Qhl, float scale)
{
    const int s = blockIdx.x, b = blockIdx.z;
    const int h = blockIdx.y * 4 + (threadIdx.x >> 5);
    const int t = threadIdx.x & 31;
    const int m = b * SS + s;
    const float tp = (float)pos[m];
    const float f = exp2f((float)t * (-13.2877123795494f / 32.f));
    float c, sn; sincosf(tp * f, &sn, &c);
    const float* src = qr + ((size_t)m * NH + h) * DROPE;
    const float x0 = src[2 * t], x1 = src[2 * t + 1];
    const float v0 = (x0 * c - x1 * sn) * scale;
    const float v1 = (x1 * c + x0 * sn) * scale;
    const size_t ob = (((size_t)(b * NH + h)) * SS + s) * DQ;
    const bf16 h0 = __float2bfloat16(v0), h1 = __float2bfloat16(v1);
    Qhh[ob + DNOPE + t]      = h0;
    Qhl[ob + DNOPE + t]      = __float2bfloat16(v0 - __bfloat162float(h0));
    Qhh[ob + DNOPE + 32 + t] = h1;
    Qhl[ob + DNOPE + 32 + t] = __float2bfloat16(v1 - __bfloat162float(h1));
}

// ------- rope on shared k_pe (from ckv) -> Khh/Khl[128..191] for all heads -------
__global__ __launch_bounds__(256)
void build_krope_k(const float* __restrict__ ckv, const int* __restrict__ pos,
                   bf16* __restrict__ Khh, bf16* __restrict__ Khl)
{
    const int s = blockIdx.x, b = blockIdx.y;
    const size_t bs = (size_t)b * SS + s;
    __shared__ float kr[DROPE];
    const int tid = threadIdx.x;
    if (tid < 32) {
        const float tp = (float)pos[bs];
        const float f = exp2f((float)tid * (-13.2877123795494f / 32.f));
        float c, sn; sincosf(tp * f, &sn, &c);
        const float x0 = ckv[bs * W1R + KVRANK + 2 * tid];
        const float x1 = ckv[bs * W1R + KVRANK + 2 * tid + 1];
        kr[tid]      = x0 * c - x1 * sn;
        kr[32 + tid] = x1 * c + x0 * sn;
    }
    __syncthreads();
    for (int idx = tid; idx < NH * DROPE; idx += 256) {
        const int h = idx >> 6, d = idx & 63;
        const float v = kr[d];
        const size_t o = (((size_t)(b * NH + h)) * SS + s) * DQ + DNOPE + d;
        const bf16 hh = __float2bfloat16(v);
        Khh[o] = hh;
        Khl[o] = __float2bfloat16(v - __bfloat162float(hh));
    }
}

// ====== HMMA flash attention, cp.async pipelined K (2-stage) + early V ======
#define FQM 128
#define FKN 64
#define FQH0 0
#define FQL0 49152
#define FKS0 98304
#define FKSTG 49152
#define FVH0 196608
#define FVL0 212992
#define FL_SMEM 229376

__global__ __launch_bounds__(256, 1)
void flashmma_k(const bf16* __restrict__ Qhh, const bf16* __restrict__ Qhl,
                const bf16* __restrict__ Khh, const bf16* __restrict__ Khl,
                const bf16* __restrict__ Vhh, const bf16* __restrict__ Vhl,
                bf16* __restrict__ ath, bf16* __restrict__ atl)
{
    extern __shared__ char sm[];
    const uint32_t sb = s2u(sm);
    const int tid = threadIdx.x, w = tid >> 5, l = tid & 31;
    const int qt = (int)gridDim.x - 1 - (int)blockIdx.x;   // heavy CTAs first
    const int bh = blockIdx.y;
    const int b = bh / NH, h = bh % NH;
    const int q0 = qt * FQM;

    {
        const uint4* Kh4 = reinterpret_cast<const uint4*>(Khh + (size_t)bh * SS * DQ);
        const uint4* Kl4 = reinterpret_cast<const uint4*>(Khl + (size_t)bh * SS * DQ);
        for (int idx = tid; idx < 64 * 24; idx += 256) {
            const int row = idx / 24, u = idx % 24;
            const int p = u >> 3, qd = u & 7;
            const uint32_t off = (uint32_t)(p * 8192) + SWZ128((uint32_t)(row * 128 + qd * 16));
            cpa16(sb + FKS0 + off,         Kh4 + row * 24 + u);
            cpa16(sb + FKS0 + 24576 + off, Kl4 + row * 24 + u);
        }
        CPA_COMMIT();
    }

    {
        const uint4* Qh4 = reinterpret_cast<const uint4*>(Qhh + ((size_t)bh * SS + q0) * DQ);
        const uint4* Ql4 = reinterpret_cast<const uint4*>(Qhl + ((size_t)bh * SS + q0) * DQ);
        for (int idx = tid; idx < 128 * 24; idx += 256) {
            const int row = idx / 24, u = idx % 24;
            const int p = u >> 3, qd = u & 7;
            const uint32_t off = (uint32_t)(p * 16384) + SWZ128((uint32_t)(row * 128 + qd * 16));
            *reinterpret_cast<uint4*>(sm + FQH0 + off) = Qh4[row * 24 + u];
            *reinterpret_cast<uint4*>(sm + FQL0 + off) = Ql4[row * 24 + u];
        }
    }

    float oacc[16][4];
    #pragma unroll
    for (int i = 0; i < 16; i++)
        #pragma unroll
        for (int e = 0; e < 4; e++) oacc[i][e] = 0.f;
    float mrow[2] = {-1e30f, -1e30f};
    float lsum[2] = {0.f, 0.f};

    const int r0 = q0 + w * 16 + (l >> 2);
    const int r1 = r0 + 8;

    const int ktmax = 2 * qt + 1;
    for (int kt = 0; kt <= ktmax; kt++) {
        const int k0 = kt * FKN;
        const uint32_t kcur = sb + FKS0 + (uint32_t)(kt & 1) * FKSTG;

        {
            const uint4* Vh4 = reinterpret_cast<const uint4*>(Vhh + ((size_t)bh * SS + k0) * DV);
            const uint4* Vl4 = reinterpret_cast<const uint4*>(Vhl + ((size_t)bh * SS + k0) * DV);
            for (int idx = tid; idx < 64 * 16; idx += 256) {
                const int row = idx >> 4, qd = idx & 15;
                const uint32_t off = SWZV((uint32_t)(row * 256 + qd * 16));
                cpa16(sb + FVH0 + off, Vh4 + row * 16 + qd);
                cpa16(sb + FVL0 + off, Vl4 + row * 16 + qd);
            }
            if (kt < ktmax) {
                const uint32_t knxt = sb + FKS0 + (uint32_t)((kt + 1) & 1) * FKSTG;
                const uint4* Kh4 = reinterpret_cast<const uint4*>(Khh + ((size_t)bh * SS + k0 + FKN) * DQ);
                const uint4* Kl4 = reinterpret_cast<const uint4*>(Khl + ((size_t)bh * SS + k0 + FKN) * DQ);
                for (int idx = tid; idx < 64 * 24; idx += 256) {
                    const int row = idx / 24, u = idx % 24;
                    const int p = u >> 3, qd = u & 7;
                    const uint32_t off = (uint32_t)(p * 8192) + SWZ128((uint32_t)(row * 128 + qd * 16));
                    cpa16(knxt + off,         Kh4 + row * 24 + u);
                    cpa16(knxt + 24576 + off, Kl4 + row * 24 + u);
                }
            }
            CPA_COMMIT();
        }
        CPA_WAIT1();
        __syncthreads();

        float sacc[8][4];
        #pragma unroll
        for (int nt = 0; nt < 8; nt++)
            #pragma unroll
            for (int e = 0; e < 4; e++) sacc[nt][e] = 0.f;

        #pragma unroll
        for (int p = 0; p < 3; p++)
            #pragma unroll
            for (int ks = 0; ks < 4; ks++) {
                uint32_t ah[4], al[4];
                const uint32_t aoff = (uint32_t)(p * 16384) +
                    SWZ128((uint32_t)((w * 16 + (l & 15)) * 128 + (ks * 2 + (l >> 4)) * 16));
                ldmx4(ah, sb + FQH0 + aoff);
                ldmx4(al, sb + FQL0 + aoff);
                #pragma unroll
                for (int nt = 0; nt < 8; nt++) {
                    uint32_t bh_[2], bl_[2];
                    const uint32_t boff = (uint32_t)(p * 8192) +
                        SWZ128((uint32_t)((nt * 8 + (l & 7)) * 128 + (ks * 2 + ((l >> 3) & 1)) * 16));
                    ldmx2(bh_, kcur + boff);
                    ldmx2(bl_, kcur + 24576 + boff);
                    mma16816(sacc[nt], ah, bh_);
                    mma16816(sacc[nt], ah, bl_);
                    mma16816(sacc[nt], al, bh_);
                }
            }

        if (kt >= 2 * qt) {
            #pragma unroll
            for (int nt = 0; nt < 8; nt++) {
                const int c0 = k0 + nt * 8 + (l & 3) * 2;
                if (c0     > r0) sacc[nt][0] = -1e30f;
                if (c0 + 1 > r0) sacc[nt][1] = -1e30f;
                if (c0     > r1) sacc[nt][2] = -1e30f;
                if (c0 + 1 > r1) sacc[nt][3] = -1e30f;
            }
        }

        float alpha[2];
        #pragma unroll
        for (int sub = 0; sub < 2; sub++) {
            float tm = -1e30f;
            #pragma unroll
            for (int nt = 0; nt < 8; nt++)
                tm = fmaxf(tm, fmaxf(sacc[nt][2 * sub], sacc[nt][2 * sub + 1]));
            tm = fmaxf(tm, __shfl_xor_sync(0xffffffffu, tm, 1));
            tm = fmaxf(tm, __shfl_xor_sync(0xffffffffu, tm, 2));
            const float mn = fmaxf(mrow[sub], tm);
            alpha[sub] = __expf(mrow[sub] - mn);
            float rs = 0.f;
            #pragma unroll
            for (int nt = 0; nt < 8; nt++) {
                sacc[nt][2 * sub]     = __expf(sacc[nt][2 * sub] - mn);
                sacc[nt][2 * sub + 1] = __expf(sacc[nt][2 * sub + 1] - mn);
                rs += sacc[nt][2 * sub] + sacc[nt][2 * sub + 1];
            }
            rs += __shfl_xor_sync(0xffffffffu, rs, 1);
            rs += __shfl_xor_sync(0xffffffffu, rs, 2);
            lsum[sub] = lsum[sub] * alpha[sub] + rs;
            mrow[sub] = mn;
        }
        #pragma unroll
        for (int ntv = 0; ntv < 16; ntv++) {
            oacc[ntv][0] *= alpha[0]; oacc[ntv][1] *= alpha[0];
            oacc[ntv][2] *= alpha[1]; oacc[ntv][3] *= alpha[1];
        }

        CPA_WAIT0();
        __syncthreads();

        #pragma unroll
        for (int kt4 = 0; kt4 < 4; kt4++) {
            uint32_t pah[4], pal[4];
            {
                const float* s0 = sacc[2 * kt4];
                const float* s1 = sacc[2 * kt4 + 1];
                float h00 = __bfloat162float(__float2bfloat16(s0[0]));
                float h01 = __bfloat162float(__float2bfloat16(s0[1]));
                float h02 = __bfloat162float(__float2bfloat16(s0[2]));
                float h03 = __bfloat162float(__float2bfloat16(s0[3]));
                float h10 = __bfloat162float(__float2bfloat16(s1[0]));
                float h11 = __bfloat162float(__float2bfloat16(s1[1]));
                float h12 = __bfloat162float(__float2bfloat16(s1[2]));
                float h13 = __bfloat162float(__float2bfloat16(s1[3]));
                pah[0] = packbf2(h00, h01); pah[1] = packbf2(h02, h03);
                pah[2] = packbf2(h10, h11); pah[3] = packbf2(h12, h13);
                pal[0] = packbf2(s0[0] - h00, s0[1] - h01);
                pal[1] = packbf2(s0[2] - h02, s0[3] - h03);
                pal[2] = packbf2(s1[0] - h10, s1[1] - h11);
                pal[3] = packbf2(s1[2] - h12, s1[3] - h13);
            }
            #pragma unroll
            for (int ntv = 0; ntv < 16; ntv++) {
                uint32_t bvh[2], bvl[2];
                const uint32_t voff =
                    SWZV((uint32_t)((kt4 * 16 + (l & 7) + ((l >> 3) & 1) * 8) * 256 + ntv * 16));
                ldmx2t(bvh, sb + FVH0 + voff);
                ldmx2t(bvl, sb + FVL0 + voff);
                mma16816(oacc[ntv], pah, bvh);
                mma16816(oacc[ntv], pah, bvl);
                mma16816(oacc[ntv], pal, bvh);
            }
        }
        __syncthreads();
    }

    const float inv0 = 1.f / lsum[0];
    const float inv1 = 1.f / lsum[1];
    const size_t row0 = (size_t)(b * SS + r0) * ODIM + h * DV;
    const size_t row1 = (size_t)(b * SS + r1) * ODIM + h * DV;
    #pragma unroll
    for (int ntv = 0; ntv < 16; ntv++) {
        const int col = ntv * 8 + (l & 3) * 2;
        st_pair(ath, atl, row0 + col, oacc[ntv][0] * inv0, oacc[ntv][1] * inv0);
        st_pair(ath, atl, row1 + col, oacc[ntv][2] * inv1, oacc[ntv][3] * inv1);
    }
}

// ---------------- launch ----------------
extern "C" void kernel_launch(void* const* d_in, const int* in_sizes, int n_in,
                              void* d_out, int out_size)
{
    const float* hidden = (const float*)d_in[0];
    const float* qaw    = (const float*)d_in[1];
    const float* qaln   = (const float*)d_in[2];
    const float* qbw    = (const float*)d_in[3];
    const float* kvaw   = (const float*)d_in[4];
    const float* kvaln  = (const float*)d_in[5];
    const float* kvbw   = (const float*)d_in[6];
    const float* ow     = (const float*)d_in[7];
    const int*   pos    = (const int*)d_in[8];
    // d_in[9] = attention_mask (causal tril) — enforced analytically in flash kernel
    float* out = (float*)d_out;

    float *c1, *qrope;
    bf16 *hidh, *hidl, *w1h, *w1l, *qbwh, *qbwl, *kvbwh, *kvbwl;
    bf16 *owh, *owl, *qch, *qcl, *cnh, *cnl, *ath, *atl;
    bf16 *Qhh, *Qhl, *Khh, *Khl, *Vhh, *Vhl;
    cudaGetSymbolAddress((void**)&c1,   g_c1);
    cudaGetSymbolAddress((void**)&qrope, g_qrope);
    cudaGetSymbolAddress((void**)&hidh, g_hidh); cudaGetSymbolAddress((void**)&hidl, g_hidl);
    cudaGetSymbolAddress((void**)&w1h, g_w1h);   cudaGetSymbolAddress((void**)&w1l, g_w1l);
    cudaGetSymbolAddress((void**)&qbwh, g_qbwh); cudaGetSymbolAddress((void**)&qbwl, g_qbwl);
    cudaGetSymbolAddress((void**)&kvbwh, g_kvbwh); cudaGetSymbolAddress((void**)&kvbwl, g_kvbwl);
    cudaGetSymbolAddress((void**)&owh, g_owh);   cudaGetSymbolAddress((void**)&owl, g_owl);
    cudaGetSymbolAddress((void**)&qch, g_qch);   cudaGetSymbolAddress((void**)&qcl, g_qcl);
    cudaGetSymbolAddress((void**)&cnh, g_cnh);   cudaGetSymbolAddress((void**)&cnl, g_cnl);
    cudaGetSymbolAddress((void**)&ath, g_ath);   cudaGetSymbolAddress((void**)&atl, g_atl);
    cudaGetSymbolAddress((void**)&Qhh, g_Qhh);   cudaGetSymbolAddress((void**)&Qhl, g_Qhl);
    cudaGetSymbolAddress((void**)&Khh, g_Khh);   cudaGetSymbolAddress((void**)&Khl, g_Khl);
    cudaGetSymbolAddress((void**)&Vhh, g_Vhh);   cudaGetSymbolAddress((void**)&Vhl, g_Vhl);

    cudaFuncSetAttribute(gemm_tc<0>, cudaFuncAttributeMaxDynamicSharedMemorySize, GEMM_SMEM);
    cudaFuncSetAttribute(gemm_tc<1>, cudaFuncAttributeMaxDynamicSharedMemorySize, GEMM_SMEM);
    cudaFuncSetAttribute(gemm_tc<2>, cudaFuncAttributeMaxDynamicSharedMemorySize, GEMM_SMEM);
    cudaFuncSetAttribute(flashmma_k, cudaFuncAttributeMaxDynamicSharedMemorySize, FL_SMEM);

    const float scale = rsqrtf((float)DQ);

    #define CVT4(x, h, l, n) cvt_pair4_k<<<(unsigned)((((size_t)(n) / 4) + 255) / 256), 256>>>(x, h, l, (size_t)(n) / 4)
    CVT4(hidden, hidh, hidl, (size_t)MTOK * HID);
    CVT4(qaw,    w1h,  w1l,  (size_t)QRANK * HID);
    cvt_pad4_k<<<(unsigned)((((size_t)KVAPAD * HID / 4) + 255) / 256), 256>>>(
        kvaw, w1h + (size_t)QRANK * HID, w1l + (size_t)QRANK * HID,
        KVAOUT, HID, KVAPAD);
    CVT4(qbw,    qbwh, qbwl, (size_t)QBOUT * QRANK);
    CVT4(kvbw,   kvbwh, kvbwl, (size_t)KVBOUT * KVRANK);
    CVT4(ow,     owh,  owl,  (size_t)HID * ODIM);

    // 1) combined [q_c | ckv] = hidden @ [q_a ; kv_a]^T   [4096, 2176]
    gemm_tc<0><<<dim3(W1R/TN, MTOK/TM), 256, GEMM_SMEM>>>(
        hidh, hidl, w1h, w1l, c1, HID, W1R,
        nullptr, nullptr, nullptr, nullptr, nullptr, 0.f);
    // 2) rmsnorm(q_c) and rmsnorm(ckv[:, :512])
    rmsnorm_pair_k<<<MTOK, 256>>>(c1, qaln, qch, qcl, QRANK, W1R);
    rmsnorm_pair_k<<<MTOK, 256>>>(c1 + QRANK, kvaln, cnh, cnl, KVRANK, W1R);
    // 3) q GEMM -> fused epilogue: Qhh/Qhl nope (scaled) + rope fp32 scratch
    gemm_tc<1><<<dim3(QBOUT/TN, MTOK/TM), 256, GEMM_SMEM>>>(
        qch, qcl, qbwh, qbwl, nullptr, QRANK, 0,
        Qhh, Qhl, nullptr, nullptr, qrope, scale);
    // 4) kv GEMM -> fused epilogue: Khh/Khl nope + Vhh/Vhl
    gemm_tc<2><<<dim3(KVBOUT/TN, MTOK/TM), 256, GEMM_SMEM>>>(
        cnh, cnl, kvbwh, kvbwl, nullptr, KVRANK, 0,
        Khh, Khl, Vhh, Vhl, nullptr, 0.f);
    // 5) rope fills: Q[128..191] from scratch; K[128..191] from ckv (all heads)
    build_qrope_k<<<dim3(SS, NH/4, BB), 128>>>(qrope, pos, Qhh, Qhl, scale);
    build_krope_k<<<dim3(SS, BB), 256>>>(c1 + QRANK, pos, Khh, Khl);
    // 6) HMMA flash attention -> attn (hi,lo) bf16
    flashmma_k<<<dim3(SS/FQM, BB*NH), 256, FL_SMEM>>>(Qhh, Qhl, Khh, Khl, Vhh, Vhl, ath, atl);
    // 7) out = attn @ o^T
    gemm_tc<0><<<dim3(HID/TN, MTOK/TM), 256, GEMM_SMEM>>>(
        ath, atl, owh, owl, out, ODIM, HID,
        nullptr, nullptr, nullptr, nullptr, nullptr, 0.f);
}